// round 11
// baseline (speedup 1.0000x reference)
#include <cuda_runtime.h>
#include <cuda_fp16.h>
#include <math.h>
#include <stdint.h>

// Problem constants (fixed shapes)
#define BB   2
#define LQ   1024
#define LK   2048
#define HH   1024
#define NH   16
#define HD   64
#define EPS  1e-5f

// -------------------- scratch --------------------
__device__ __align__(256) __half w16q[HH * HH];
__device__ __align__(256) __half w16k[HH * HH];
__device__ __align__(256) __half w16v[HH * HH];
__device__ __align__(256) __half w16o[HH * HH];
__device__ __align__(256) __half g_Q16[BB * LQ * HH];
__device__ __align__(256) __half g_K16[BB * LK * HH];
__device__ __align__(256) __half g_V16[BB * LK * HH];
__device__ __align__(256) __half g_ctx16[BB * LQ * HH];
__device__ __align__(256) float  g_x[BB * LQ * HH];

// -------------------- helpers --------------------
__device__ __forceinline__ uint32_t smaddr(const void* p) {
    return (uint32_t)__cvta_generic_to_shared(p);
}
__device__ __forceinline__ void cp16(uint32_t dst, const void* src) {
    asm volatile("cp.async.cg.shared.global [%0], [%1], 16;" :: "r"(dst), "l"(src));
}
__device__ __forceinline__ void cp_commit() {
    asm volatile("cp.async.commit_group;");
}
__device__ __forceinline__ void cp_wait0() {
    asm volatile("cp.async.wait_group 0;");
}
__device__ __forceinline__ void cp_wait1() {
    asm volatile("cp.async.wait_group 1;");
}
__device__ __forceinline__ void mma16(float* c,
    uint32_t a0, uint32_t a1, uint32_t a2, uint32_t a3,
    uint32_t b0, uint32_t b1)
{
    asm volatile(
        "mma.sync.aligned.m16n8k16.row.col.f32.f16.f16.f32 "
        "{%0,%1,%2,%3},{%4,%5,%6,%7},{%8,%9},{%0,%1,%2,%3};"
        : "+f"(c[0]), "+f"(c[1]), "+f"(c[2]), "+f"(c[3])
        : "r"(a0), "r"(a1), "r"(a2), "r"(a3), "r"(b0), "r"(b1));
}
__device__ __forceinline__ void ldsm4(uint32_t& r0, uint32_t& r1, uint32_t& r2,
                                      uint32_t& r3, uint32_t a)
{
    asm volatile("ldmatrix.sync.aligned.m8n8.x4.shared.b16 {%0,%1,%2,%3}, [%4];"
                 : "=r"(r0), "=r"(r1), "=r"(r2), "=r"(r3) : "r"(a));
}
__device__ __forceinline__ void ldsm4t(uint32_t& r0, uint32_t& r1, uint32_t& r2,
                                       uint32_t& r3, uint32_t a)
{
    asm volatile("ldmatrix.sync.aligned.m8n8.x4.trans.shared.b16 {%0,%1,%2,%3}, [%4];"
                 : "=r"(r0), "=r"(r1), "=r"(r2), "=r"(r3) : "r"(a));
}
__device__ __forceinline__ uint32_t ph2(float x, float y) {
    __half2 h = __floats2half2_rn(x, y);
    return *reinterpret_cast<uint32_t*>(&h);
}

// -------------------- fp32 -> fp16 conversion (weights only) --------------------
struct CvtArgs {
    const float* src[7];
    __half* dst[7];
    int bstart[8];
};

__global__ __launch_bounds__(256) void cvt_f16(CvtArgs a)
{
    int bid = blockIdx.x, s = 0;
#pragma unroll
    for (int i = 1; i < 7; i++) if (bid >= a.bstart[i]) s = i;
    int off = (bid - a.bstart[s]) * 2048 + threadIdx.x * 8;
    float4 v0 = *reinterpret_cast<const float4*>(a.src[s] + off);
    float4 v1 = *reinterpret_cast<const float4*>(a.src[s] + off + 4);
    __half2 h0 = __floats2half2_rn(v0.x, v0.y);
    __half2 h1 = __floats2half2_rn(v0.z, v0.w);
    __half2 h2 = __floats2half2_rn(v1.x, v1.y);
    __half2 h3 = __floats2half2_rn(v1.z, v1.w);
    uint4 o;
    o.x = *reinterpret_cast<uint32_t*>(&h0);
    o.y = *reinterpret_cast<uint32_t*>(&h1);
    o.z = *reinterpret_cast<uint32_t*>(&h2);
    o.w = *reinterpret_cast<uint32_t*>(&h3);
    *reinterpret_cast<uint4*>(a.dst[s] + off) = o;
}

// -------------------- fp16 GEMM (templated): C = A @ W^T + bias -----------------
// CTA tile 128(M) x NT(N), BK=32, 3-stage cp.async ring, 256 threads = 8 warps.
// A32=1: A operand is fp32 in gmem/smem; fragments converted at load (rn).
struct GemmSeg {
    const void* A; const __half* W;
    const float* bias; const float* residual;
    void* C; int outHalf; int tileStart;
};
struct GemmArgs { GemmSeg seg[3]; int nseg; };

template<int NT, int A32>
__global__ __launch_bounds__(256, 2) void gemm_f16(GemmArgs ga)
{
    constexpr int NI = NT / 16;
    constexpr int AST = A32 ? 36 : 20;       // words per A row
    constexpr int ASTG = 128 * AST;          // words per A stage
    constexpr int BSTG = NT * 20;            // words per B stage
    extern __shared__ __align__(16) uint32_t dsm[];
    uint32_t* Asm = dsm;                     // [3][ASTG]
    uint32_t* Bsm = dsm + 3 * ASTG;          // [3][BSTG]

    const int y = blockIdx.y;
    int si = 0;
#pragma unroll
    for (int i = 1; i < 3; i++) if (i < ga.nseg && y >= ga.seg[i].tileStart) si = i;
    const GemmSeg sg = ga.seg[si];

    const int t = threadIdx.x, lane = t & 31, warp = t >> 5;
    const int g = lane >> 2, tg = lane & 3;
    const int wm = warp & 3, wn = warp >> 2;
    const int rowBase = (y - sg.tileStart) * 128, colBase = blockIdx.x * NT;
    const uint32_t smA = smaddr(Asm), smB = smaddr(Bsm);

    auto loadStage = [&](int buf, int k0) {
        if (A32) {
            const float* Ap = (const float*)sg.A;
#pragma unroll
            for (int i = 0; i < 4; i++) {         // 128 rows x 128B, 8 chunks/row
                int id = t + 256 * i;
                int r = id >> 3, c = (id & 7) * 16;
                cp16(smA + (uint32_t)(buf * ASTG * 4 + r * 144 + c),
                     Ap + (size_t)(rowBase + r) * HH + k0 + (c >> 2));
            }
        } else {
            const __half* Ap = (const __half*)sg.A;
#pragma unroll
            for (int i = 0; i < 2; i++) {         // 128 rows x 64B, 4 chunks/row
                int id = t + 256 * i;
                int r = id >> 2, c = (id & 3) * 8;
                cp16(smA + (uint32_t)(buf * ASTG * 4 + r * 80 + c * 2),
                     Ap + (size_t)(rowBase + r) * HH + k0 + c);
            }
        }
#pragma unroll
        for (int i = 0; i < NT / 64; i++) {
            int id = t + 256 * i;
            int r = id >> 2, c = (id & 3) * 8;
            cp16(smB + (uint32_t)(buf * BSTG * 4 + r * 80 + c * 2),
                 sg.W + (size_t)(colBase + r) * HH + k0 + c);
        }
    };

    loadStage(0, 0);  cp_commit();
    loadStage(1, 32); cp_commit();

    float acc[2][NI][4] = {};
    const int nst = HH / 32;

    for (int s = 0; s < nst; s++) {
        if (s + 1 < nst) cp_wait1(); else cp_wait0();
        __syncthreads();
        if (s + 2 < nst) { loadStage((s + 2) % 3, (s + 2) * 32); cp_commit(); }

        const uint32_t* Ac = Asm + (s % 3) * ASTG;
        const uint32_t* Bc = Bsm + (s % 3) * BSTG;

#pragma unroll
        for (int k16 = 0; k16 < 2; k16++) {
            uint32_t a[2][4];
#pragma unroll
            for (int mi = 0; mi < 2; mi++) {
                int r = wm * 32 + mi * 16 + g;
                if (A32) {
                    float2 v0 = *reinterpret_cast<const float2*>(Ac + r * 36 + k16 * 16 + tg * 2);
                    float2 v1 = *reinterpret_cast<const float2*>(Ac + (r + 8) * 36 + k16 * 16 + tg * 2);
                    float2 v2 = *reinterpret_cast<const float2*>(Ac + r * 36 + k16 * 16 + 8 + tg * 2);
                    float2 v3 = *reinterpret_cast<const float2*>(Ac + (r + 8) * 36 + k16 * 16 + 8 + tg * 2);
                    a[mi][0] = ph2(v0.x, v0.y);
                    a[mi][1] = ph2(v1.x, v1.y);
                    a[mi][2] = ph2(v2.x, v2.y);
                    a[mi][3] = ph2(v3.x, v3.y);
                } else {
                    a[mi][0] = Ac[r * 20 + k16 * 8 + tg];
                    a[mi][1] = Ac[(r + 8) * 20 + k16 * 8 + tg];
                    a[mi][2] = Ac[r * 20 + k16 * 8 + 4 + tg];
                    a[mi][3] = Ac[(r + 8) * 20 + k16 * 8 + 4 + tg];
                }
            }
#pragma unroll
            for (int ni = 0; ni < NI; ni++) {
                int n = wn * (NT / 2) + ni * 8 + g;
                uint32_t b0 = Bc[n * 20 + k16 * 8 + tg];
                uint32_t b1 = Bc[n * 20 + k16 * 8 + 4 + tg];
                mma16(acc[0][ni], a[0][0], a[0][1], a[0][2], a[0][3], b0, b1);
                mma16(acc[1][ni], a[1][0], a[1][1], a[1][2], a[1][3], b0, b1);
            }
        }
    }

#pragma unroll
    for (int mi = 0; mi < 2; mi++) {
#pragma unroll
        for (int ni = 0; ni < NI; ni++) {
            int r = rowBase + wm * 32 + mi * 16 + g;
            int c = colBase + wn * (NT / 2) + ni * 8 + tg * 2;
            float b0 = sg.bias[c], b1 = sg.bias[c + 1];
            float v0 = acc[mi][ni][0] + b0, v1 = acc[mi][ni][1] + b1;
            float v2 = acc[mi][ni][2] + b0, v3 = acc[mi][ni][3] + b1;
            if (sg.outHalf) {
                __half* Ch = (__half*)sg.C;
                *reinterpret_cast<__half2*>(Ch + (size_t)r * HH + c) = __floats2half2_rn(v0, v1);
                *reinterpret_cast<__half2*>(Ch + (size_t)(r + 8) * HH + c) = __floats2half2_rn(v2, v3);
            } else {
                float* Cf = (float*)sg.C;
                if (sg.residual) {
                    float2 r0 = *reinterpret_cast<const float2*>(sg.residual + (size_t)r * HH + c);
                    float2 r1 = *reinterpret_cast<const float2*>(sg.residual + (size_t)(r + 8) * HH + c);
                    v0 += r0.x; v1 += r0.y; v2 += r1.x; v3 += r1.y;
                }
                *reinterpret_cast<float2*>(Cf + (size_t)r * HH + c) = make_float2(v0, v1);
                *reinterpret_cast<float2*>(Cf + (size_t)(r + 8) * HH + c) = make_float2(v2, v3);
            }
        }
    }
}

#define G128_SMEM (3 * (128 * 36 + 128 * 20) * 4)   // 86016
#define G64_SMEM  (3 * (128 * 20 + 64 * 20) * 4)    // 46080

// -------------------- Flash attention v9: 3-stage K/V pipeline ------------------
// CTA: 128 q-rows of one (b,h), 256 threads = 8 warps; warp = 16 rows x 64 cols.
// K/V fp16 smem (144B stride), B-frags via ldmatrix, P in registers.
#define KVW 2304                               // words per K (or V) stage
#define A3_BYTES (3 * KVW * 2 * 4)             // 55296 bytes -> 2 CTAs/SM

__global__ __launch_bounds__(256, 2) void attn_f16(
    const __half* __restrict__ Q, const __half* __restrict__ K,
    const __half* __restrict__ V, const int* __restrict__ mask,
    __half* __restrict__ ctx)
{
    extern __shared__ __align__(16) uint32_t sh[];
    uint32_t* Kw = sh;
    uint32_t* Vw = sh + 3 * KVW;

    const int q0 = blockIdx.x * 128, h = blockIdx.y, b = blockIdx.z;
    const int t = threadIdx.x, lane = t & 31, warp = t >> 5;
    const int g = lane >> 2, tg = lane & 3;
    const int wbase = warp * 16;
    const int ti = lane >> 3, r8 = lane & 7;
    const int knRow = ((ti >> 1) << 3) + r8;
    const int kCol  = ti & 1;
    const int vRow  = ((ti & 1) << 3) + r8;
    const int vCol  = ti >> 1;

    const uint32_t smK = smaddr(Kw), smV = smaddr(Vw);

    // stage Q through the V region, extract fragments
#pragma unroll
    for (int i = 0; i < 4; i++) {
        int id = t + 256 * i;
        int r = id >> 3, c = id & 7;
        cp16(smV + (uint32_t)(r * 144 + c * 16),
             Q + (size_t)(b * LQ + q0 + r) * HH + h * HD + c * 8);
    }
    cp_commit(); cp_wait0(); __syncthreads();

    uint32_t qf[4][4];
    {
        int r0 = wbase + g, r1 = r0 + 8;
#pragma unroll
        for (int k16 = 0; k16 < 4; k16++) {
            qf[k16][0] = Vw[r0 * 36 + k16 * 8 + tg];
            qf[k16][1] = Vw[r1 * 36 + k16 * 8 + tg];
            qf[k16][2] = Vw[r0 * 36 + k16 * 8 + 4 + tg];
            qf[k16][3] = Vw[r1 * 36 + k16 * 8 + 4 + tg];
        }
    }
    __syncthreads();

    auto loadKV = [&](int s, int k0) {
#pragma unroll
        for (int i = 0; i < 2; i++) {
            int id = t + 256 * i;
            int r = id >> 3, c = id & 7;
            size_t gofs = (size_t)(b * LK + k0 + r) * HH + h * HD + c * 8;
            cp16(smK + (uint32_t)(s * KVW * 4 + r * 144 + c * 16), K + gofs);
            cp16(smV + (uint32_t)(s * KVW * 4 + r * 144 + c * 16), V + gofs);
        }
    };
    loadKV(0, 0);  cp_commit();
    loadKV(1, 64); cp_commit();

    float acc[8][4] = {};
    float m0 = -1e30f, m1 = -1e30f, l0 = 0.f, l1 = 0.f;
    const int* mbase = mask + (size_t)(b * LQ + q0) * LK;
    const int nkt = LK / 64;
    const int r0 = wbase + g, r1 = r0 + 8;

    for (int kt = 0; kt < nkt; kt++) {
        if (kt + 1 < nkt) cp_wait1(); else cp_wait0();
        __syncthreads();
        if (kt + 2 < nkt) { loadKV((kt + 2) % 3, (kt + 2) * 64); cp_commit(); }

        const uint32_t kcB = smK + (uint32_t)((kt % 3) * KVW * 4);
        const uint32_t vcB = smV + (uint32_t)((kt % 3) * KVW * 4);

        int2 mk0[8], mk1[8];
#pragma unroll
        for (int ni = 0; ni < 8; ni++) {
            int c = ni * 8 + tg * 2;
            mk0[ni] = *reinterpret_cast<const int2*>(mbase + (size_t)r0 * LK + kt * 64 + c);
            mk1[ni] = *reinterpret_cast<const int2*>(mbase + (size_t)r1 * LK + kt * 64 + c);
        }

        // S = Q K^T
        float s[8][4] = {};
#pragma unroll
        for (int k16 = 0; k16 < 4; k16++) {
#pragma unroll
            for (int nip = 0; nip < 4; nip++) {
                uint32_t b0, b1, b2, b3;
                uint32_t addr = kcB + (uint32_t)((nip * 16 + knRow) * 144
                                                 + (k16 * 2 + kCol) * 16);
                ldsm4(b0, b1, b2, b3, addr);
                mma16(s[2 * nip], qf[k16][0], qf[k16][1], qf[k16][2], qf[k16][3], b0, b1);
                mma16(s[2 * nip + 1], qf[k16][0], qf[k16][1], qf[k16][2], qf[k16][3], b2, b3);
            }
        }

        // mask + scale, row max
        float mx0 = m0, mx1 = m1;
#pragma unroll
        for (int ni = 0; ni < 8; ni++) {
            s[ni][0] = (mk0[ni].x == 0) ? -1e9f : s[ni][0] * 0.125f;
            s[ni][1] = (mk0[ni].y == 0) ? -1e9f : s[ni][1] * 0.125f;
            s[ni][2] = (mk1[ni].x == 0) ? -1e9f : s[ni][2] * 0.125f;
            s[ni][3] = (mk1[ni].y == 0) ? -1e9f : s[ni][3] * 0.125f;
            mx0 = fmaxf(mx0, fmaxf(s[ni][0], s[ni][1]));
            mx1 = fmaxf(mx1, fmaxf(s[ni][2], s[ni][3]));
        }
        mx0 = fmaxf(mx0, __shfl_xor_sync(0xffffffff, mx0, 1));
        mx0 = fmaxf(mx0, __shfl_xor_sync(0xffffffff, mx0, 2));
        mx1 = fmaxf(mx1, __shfl_xor_sync(0xffffffff, mx1, 1));
        mx1 = fmaxf(mx1, __shfl_xor_sync(0xffffffff, mx1, 2));

        float al0 = __expf(m0 - mx0), al1 = __expf(m1 - mx1);
        float ls0 = 0.f, ls1 = 0.f;
#pragma unroll
        for (int ni = 0; ni < 8; ni++) {
            s[ni][0] = __expf(s[ni][0] - mx0);
            s[ni][1] = __expf(s[ni][1] - mx0);
            s[ni][2] = __expf(s[ni][2] - mx1);
            s[ni][3] = __expf(s[ni][3] - mx1);
            ls0 += s[ni][0] + s[ni][1];
            ls1 += s[ni][2] + s[ni][3];
        }
        ls0 += __shfl_xor_sync(0xffffffff, ls0, 1);
        ls0 += __shfl_xor_sync(0xffffffff, ls0, 2);
        ls1 += __shfl_xor_sync(0xffffffff, ls1, 1);
        ls1 += __shfl_xor_sync(0xffffffff, ls1, 2);
        l0 = l0 * al0 + ls0;  m0 = mx0;
        l1 = l1 * al1 + ls1;  m1 = mx1;

        // rescale accumulator; pack P to fp16 A-fragments (registers only)
        uint32_t pa[4][4];
#pragma unroll
        for (int ni = 0; ni < 8; ni++) {
            acc[ni][0] *= al0; acc[ni][1] *= al0;
            acc[ni][2] *= al1; acc[ni][3] *= al1;
        }
#pragma unroll
        for (int k16 = 0; k16 < 4; k16++) {
            pa[k16][0] = ph2(s[2 * k16][0], s[2 * k16][1]);
            pa[k16][1] = ph2(s[2 * k16][2], s[2 * k16][3]);
            pa[k16][2] = ph2(s[2 * k16 + 1][0], s[2 * k16 + 1][1]);
            pa[k16][3] = ph2(s[2 * k16 + 1][2], s[2 * k16 + 1][3]);
        }

        // O += P @ V
#pragma unroll
        for (int k16 = 0; k16 < 4; k16++) {
#pragma unroll
            for (int nip = 0; nip < 4; nip++) {
                uint32_t b0, b1, b2, b3;
                uint32_t addr = vcB + (uint32_t)((k16 * 16 + vRow) * 144
                                                 + (nip * 2 + vCol) * 16);
                ldsm4t(b0, b1, b2, b3, addr);
                mma16(acc[2 * nip], pa[k16][0], pa[k16][1], pa[k16][2], pa[k16][3], b0, b1);
                mma16(acc[2 * nip + 1], pa[k16][0], pa[k16][1], pa[k16][2], pa[k16][3], b2, b3);
            }
        }
    }

    // epilogue: ctx fp16
    {
        float inv0 = 1.f / l0, inv1 = 1.f / l1;
#pragma unroll
        for (int ni = 0; ni < 8; ni++) {
            int c = ni * 8 + tg * 2;
            size_t o0 = (size_t)(b * LQ + q0 + r0) * HH + h * HD + c;
            size_t o1 = (size_t)(b * LQ + q0 + r1) * HH + h * HD + c;
            *reinterpret_cast<__half2*>(ctx + o0) =
                __floats2half2_rn(acc[ni][0] * inv0, acc[ni][1] * inv0);
            *reinterpret_cast<__half2*>(ctx + o1) =
                __floats2half2_rn(acc[ni][2] * inv1, acc[ni][3] * inv1);
        }
    }
}

// -------------------- LayerNorm --------------------
__device__ __forceinline__ float block_reduce_sum(float v)
{
    __shared__ float red[8];
    __shared__ float tot;
    __syncthreads();
#pragma unroll
    for (int o = 16; o > 0; o >>= 1) v += __shfl_xor_sync(0xffffffff, v, o);
    int w = threadIdx.x >> 5;
    if ((threadIdx.x & 31) == 0) red[w] = v;
    __syncthreads();
    if (threadIdx.x < 32) {
        float r = (threadIdx.x < 8) ? red[threadIdx.x] : 0.f;
#pragma unroll
        for (int o = 4; o > 0; o >>= 1) r += __shfl_xor_sync(0xffffffff, r, o);
        if (threadIdx.x == 0) tot = r;
    }
    __syncthreads();
    return tot;
}

__global__ __launch_bounds__(256) void ln_kernel(
    const float* __restrict__ X, const float* __restrict__ g,
    const float* __restrict__ bta, float* __restrict__ out)
{
    int row = blockIdx.x;
    const float4 x4 = reinterpret_cast<const float4*>(X + (size_t)row * HH)[threadIdx.x];
    float v[4] = {x4.x, x4.y, x4.z, x4.w};
    float s = v[0] + v[1] + v[2] + v[3];
    float mean = block_reduce_sum(s) * (1.f / (float)HH);
    float d2 = 0.f;
#pragma unroll
    for (int j = 0; j < 4; j++) { float d = v[j] - mean; d2 += d * d; }
    float var = block_reduce_sum(d2) * (1.f / (float)HH);
    float rstd = rsqrtf(var + EPS);
    float4 g4 = reinterpret_cast<const float4*>(g)[threadIdx.x];
    float4 b4 = reinterpret_cast<const float4*>(bta)[threadIdx.x];
    float4 o;
    o.x = (v[0] - mean) * rstd * g4.x + b4.x;
    o.y = (v[1] - mean) * rstd * g4.y + b4.y;
    o.z = (v[2] - mean) * rstd * g4.z + b4.z;
    o.w = (v[3] - mean) * rstd * g4.w + b4.w;
    reinterpret_cast<float4*>(out + (size_t)row * HH)[threadIdx.x] = o;
}

// -------------------- launch --------------------
extern "C" void kernel_launch(void* const* d_in, const int* in_sizes, int n_in,
                              void* d_out, int out_size)
{
    const float* query = (const float*)d_in[0];
    const float* key   = (const float*)d_in[1];
    const float* value = (const float*)d_in[2];
    const int*   mask  = (const int*)d_in[3];
    const float* bq = (const float*)d_in[5];
    const float* bk = (const float*)d_in[7];
    const float* bv = (const float*)d_in[9];
    const float* bo = (const float*)d_in[11];
    const float* ln_g = (const float*)d_in[12];
    const float* ln_b = (const float*)d_in[13];
    float* out = (float*)d_out;

    __half *pwq, *pwk, *pwv, *pwo, *pQ16, *pK16, *pV16, *pctx;
    float *pX;
    cudaGetSymbolAddress((void**)&pwq, w16q);
    cudaGetSymbolAddress((void**)&pwk, w16k);
    cudaGetSymbolAddress((void**)&pwv, w16v);
    cudaGetSymbolAddress((void**)&pwo, w16o);
    cudaGetSymbolAddress((void**)&pQ16, g_Q16);
    cudaGetSymbolAddress((void**)&pK16, g_K16);
    cudaGetSymbolAddress((void**)&pV16, g_V16);
    cudaGetSymbolAddress((void**)&pctx, g_ctx16);
    cudaGetSymbolAddress((void**)&pX, g_x);

    cudaFuncSetAttribute(attn_f16,
                         cudaFuncAttributeMaxDynamicSharedMemorySize, A3_BYTES);
    cudaFuncSetAttribute(gemm_f16<128, 1>,
                         cudaFuncAttributeMaxDynamicSharedMemorySize, G128_SMEM);
    cudaFuncSetAttribute(gemm_f16<64, 0>,
                         cudaFuncAttributeMaxDynamicSharedMemorySize, G64_SMEM);

    // 1) convert weights only to fp16 (4 x 512 blocks)
    CvtArgs ca;
    ca.src[0] = (const float*)d_in[4];  ca.dst[0] = pwq;
    ca.src[1] = (const float*)d_in[6];  ca.dst[1] = pwk;
    ca.src[2] = (const float*)d_in[8];  ca.dst[2] = pwv;
    ca.src[3] = (const float*)d_in[10]; ca.dst[3] = pwo;
    ca.src[4] = ca.src[0]; ca.dst[4] = pwq;
    ca.src[5] = ca.src[0]; ca.dst[5] = pwq;
    ca.src[6] = ca.src[0]; ca.dst[6] = pwq;
    int bs[8] = {0, 512, 1024, 1536, 1 << 30, 1 << 30, 1 << 30, 1 << 30};
    for (int i = 0; i < 8; i++) ca.bstart[i] = bs[i];
    cvt_f16<<<2048, 256>>>(ca);

    // 2) fused Q/K/V projections: fp32 activations in, fp16 out
    GemmArgs qa;
    qa.nseg = 3;
    qa.seg[0] = {query, pwq, bq, nullptr, (void*)pQ16, 1, 0};
    qa.seg[1] = {key,   pwk, bk, nullptr, (void*)pK16, 1, 16};
    qa.seg[2] = {value, pwv, bv, nullptr, (void*)pV16, 1, 48};
    gemm_f16<128, 1><<<dim3(HH / 128, 80), 256, G128_SMEM>>>(qa);

    // 3) attention
    attn_f16<<<dim3(LQ / 128, NH, BB), 256, A3_BYTES>>>(pQ16, pK16, pV16, mask, pctx);

    // 4) output projection + residual (fp16 A from attention)
    GemmArgs oa;
    oa.nseg = 1;
    oa.seg[0] = {pctx, pwo, bo, query, (void*)pX, 0, 0};
    oa.seg[1] = oa.seg[0];
    oa.seg[2] = oa.seg[0];
    gemm_f16<64, 0><<<dim3(HH / 64, 16), 256, G64_SMEM>>>(oa);

    // 5) layernorm
    ln_kernel<<<BB * LQ, 256>>>(pX, ln_g, ln_b, out);
}

// round 12
// speedup vs baseline: 1.1170x; 1.1170x over previous
#include <cuda_runtime.h>
#include <cuda_fp16.h>
#include <math.h>
#include <stdint.h>

// Problem constants (fixed shapes)
#define BB   2
#define LQ   1024
#define LK   2048
#define HH   1024
#define NH   16
#define HD   64
#define EPS  1e-5f

// -------------------- scratch --------------------
__device__ __align__(256) __half c_q16[BB * LQ * HH];
__device__ __align__(256) __half c_k16[BB * LK * HH];
__device__ __align__(256) __half c_v16[BB * LK * HH];
__device__ __align__(256) __half w16q[HH * HH];
__device__ __align__(256) __half w16k[HH * HH];
__device__ __align__(256) __half w16v[HH * HH];
__device__ __align__(256) __half w16o[HH * HH];
__device__ __align__(256) __half g_Q16[BB * LQ * HH];
__device__ __align__(256) __half g_K16[BB * LK * HH];
__device__ __align__(256) __half g_V16[BB * LK * HH];
__device__ __align__(256) __half g_ctx16[BB * LQ * HH];
__device__ __align__(256) float  g_x[BB * LQ * HH];

// -------------------- helpers --------------------
__device__ __forceinline__ uint32_t smaddr(const void* p) {
    return (uint32_t)__cvta_generic_to_shared(p);
}
__device__ __forceinline__ void cp16(uint32_t dst, const void* src) {
    asm volatile("cp.async.cg.shared.global [%0], [%1], 16;" :: "r"(dst), "l"(src));
}
__device__ __forceinline__ void cp_commit() {
    asm volatile("cp.async.commit_group;");
}
__device__ __forceinline__ void cp_wait0() {
    asm volatile("cp.async.wait_group 0;");
}
__device__ __forceinline__ void cp_wait1() {
    asm volatile("cp.async.wait_group 1;");
}
__device__ __forceinline__ void mma16(float* c,
    uint32_t a0, uint32_t a1, uint32_t a2, uint32_t a3,
    uint32_t b0, uint32_t b1)
{
    asm volatile(
        "mma.sync.aligned.m16n8k16.row.col.f32.f16.f16.f32 "
        "{%0,%1,%2,%3},{%4,%5,%6,%7},{%8,%9},{%0,%1,%2,%3};"
        : "+f"(c[0]), "+f"(c[1]), "+f"(c[2]), "+f"(c[3])
        : "r"(a0), "r"(a1), "r"(a2), "r"(a3), "r"(b0), "r"(b1));
}
__device__ __forceinline__ void ldsm4(uint32_t& r0, uint32_t& r1, uint32_t& r2,
                                      uint32_t& r3, uint32_t a)
{
    asm volatile("ldmatrix.sync.aligned.m8n8.x4.shared.b16 {%0,%1,%2,%3}, [%4];"
                 : "=r"(r0), "=r"(r1), "=r"(r2), "=r"(r3) : "r"(a));
}
__device__ __forceinline__ void ldsm4t(uint32_t& r0, uint32_t& r1, uint32_t& r2,
                                       uint32_t& r3, uint32_t a)
{
    asm volatile("ldmatrix.sync.aligned.m8n8.x4.trans.shared.b16 {%0,%1,%2,%3}, [%4];"
                 : "=r"(r0), "=r"(r1), "=r"(r2), "=r"(r3) : "r"(a));
}
__device__ __forceinline__ uint32_t ph2(float x, float y) {
    __half2 h = __floats2half2_rn(x, y);
    return *reinterpret_cast<uint32_t*>(&h);
}

// -------------------- fp32 -> fp16 conversion --------------------
struct CvtArgs {
    const float* src[7];
    __half* dst[7];
    int bstart[8];
};

__global__ __launch_bounds__(256) void cvt_f16(CvtArgs a)
{
    int bid = blockIdx.x, s = 0;
#pragma unroll
    for (int i = 1; i < 7; i++) if (bid >= a.bstart[i]) s = i;
    int off = (bid - a.bstart[s]) * 2048 + threadIdx.x * 8;
    float4 v0 = *reinterpret_cast<const float4*>(a.src[s] + off);
    float4 v1 = *reinterpret_cast<const float4*>(a.src[s] + off + 4);
    __half2 h0 = __floats2half2_rn(v0.x, v0.y);
    __half2 h1 = __floats2half2_rn(v0.z, v0.w);
    __half2 h2 = __floats2half2_rn(v1.x, v1.y);
    __half2 h3 = __floats2half2_rn(v1.z, v1.w);
    uint4 o;
    o.x = *reinterpret_cast<uint32_t*>(&h0);
    o.y = *reinterpret_cast<uint32_t*>(&h1);
    o.z = *reinterpret_cast<uint32_t*>(&h2);
    o.w = *reinterpret_cast<uint32_t*>(&h3);
    *reinterpret_cast<uint4*>(a.dst[s] + off) = o;
}

// -------------------- fp16 GEMM (templated N-tile): C = A @ W^T + bias ---------
// CTA tile 128(M) x NT(N), BK=32, double-buffered cp.async, 256 threads =
// 8 warps (4M x 2N). launch_bounds(256,2) -> 2 CTAs/SM.
struct GemmSeg {
    const __half* A; const __half* W;
    const float* bias; const float* residual;
    void* C; int outHalf; int tileStart;
};
struct GemmArgs { GemmSeg seg[3]; int nseg; };

template<int NT>
__global__ __launch_bounds__(256, 2) void gemm_f16(GemmArgs ga)
{
    constexpr int NI = NT / 16;
    __shared__ __align__(16) uint32_t Asm[2 * 128 * 20];
    __shared__ __align__(16) uint32_t Bsm[2 * NT * 20];

    const int y = blockIdx.y;
    int si = 0;
#pragma unroll
    for (int i = 1; i < 3; i++) if (i < ga.nseg && y >= ga.seg[i].tileStart) si = i;
    const GemmSeg sg = ga.seg[si];

    const int t = threadIdx.x, lane = t & 31, warp = t >> 5;
    const int g = lane >> 2, tg = lane & 3;
    const int wm = warp & 3, wn = warp >> 2;
    const int rowBase = (y - sg.tileStart) * 128, colBase = blockIdx.x * NT;
    const uint32_t smA = smaddr(Asm), smB = smaddr(Bsm);

    auto loadStage = [&](int buf, int k0) {
#pragma unroll
        for (int i = 0; i < 2; i++) {
            int id = t + 256 * i;
            int r = id >> 2, c = (id & 3) * 8;
            cp16(smA + (uint32_t)(buf * 10240 + r * 80 + c * 2),
                 sg.A + (size_t)(rowBase + r) * HH + k0 + c);
        }
#pragma unroll
        for (int i = 0; i < NT / 64; i++) {
            int id = t + 256 * i;
            int r = id >> 2, c = (id & 3) * 8;
            cp16(smB + (uint32_t)(buf * (NT * 80) + r * 80 + c * 2),
                 sg.W + (size_t)(colBase + r) * HH + k0 + c);
        }
    };

    loadStage(0, 0);
    cp_commit();

    float acc[2][NI][4] = {};
    const int nst = HH / 32;

    for (int s = 0; s < nst; s++) {
        cp_wait0();
        __syncthreads();
        if (s + 1 < nst) { loadStage((s + 1) & 1, (s + 1) * 32); cp_commit(); }

        const uint32_t* Ac = Asm + (s & 1) * 2560;
        const uint32_t* Bc = Bsm + (s & 1) * (NT * 20);

#pragma unroll
        for (int k16 = 0; k16 < 2; k16++) {
            uint32_t a[2][4];
#pragma unroll
            for (int mi = 0; mi < 2; mi++) {
                int r = wm * 32 + mi * 16 + g;
                a[mi][0] = Ac[r * 20 + k16 * 8 + tg];
                a[mi][1] = Ac[(r + 8) * 20 + k16 * 8 + tg];
                a[mi][2] = Ac[r * 20 + k16 * 8 + 4 + tg];
                a[mi][3] = Ac[(r + 8) * 20 + k16 * 8 + 4 + tg];
            }
#pragma unroll
            for (int ni = 0; ni < NI; ni++) {
                int n = wn * (NT / 2) + ni * 8 + g;
                uint32_t b0 = Bc[n * 20 + k16 * 8 + tg];
                uint32_t b1 = Bc[n * 20 + k16 * 8 + 4 + tg];
                mma16(acc[0][ni], a[0][0], a[0][1], a[0][2], a[0][3], b0, b1);
                mma16(acc[1][ni], a[1][0], a[1][1], a[1][2], a[1][3], b0, b1);
            }
        }
    }

#pragma unroll
    for (int mi = 0; mi < 2; mi++) {
#pragma unroll
        for (int ni = 0; ni < NI; ni++) {
            int r = rowBase + wm * 32 + mi * 16 + g;
            int c = colBase + wn * (NT / 2) + ni * 8 + tg * 2;
            float b0 = sg.bias[c], b1 = sg.bias[c + 1];
            float v0 = acc[mi][ni][0] + b0, v1 = acc[mi][ni][1] + b1;
            float v2 = acc[mi][ni][2] + b0, v3 = acc[mi][ni][3] + b1;
            if (sg.outHalf) {
                __half* Ch = (__half*)sg.C;
                *reinterpret_cast<__half2*>(Ch + (size_t)r * HH + c) = __floats2half2_rn(v0, v1);
                *reinterpret_cast<__half2*>(Ch + (size_t)(r + 8) * HH + c) = __floats2half2_rn(v2, v3);
            } else {
                float* Cf = (float*)sg.C;
                if (sg.residual) {
                    float2 r0 = *reinterpret_cast<const float2*>(sg.residual + (size_t)r * HH + c);
                    float2 r1 = *reinterpret_cast<const float2*>(sg.residual + (size_t)(r + 8) * HH + c);
                    v0 += r0.x; v1 += r0.y; v2 += r1.x; v3 += r1.y;
                }
                *reinterpret_cast<float2*>(Cf + (size_t)r * HH + c) = make_float2(v0, v1);
                *reinterpret_cast<float2*>(Cf + (size_t)(r + 8) * HH + c) = make_float2(v2, v3);
            }
        }
    }
}

// -------------------- Flash attention v9: 3-stage K/V ring, ldsm, register P ---
// CTA: 128 q-rows of one (b,h), 256 threads = 8 warps; warp = 16 rows x 64 cols.
// K/V fp16 smem (144B stride), B-frags via ldmatrix, P in registers.
#define KVW 2304                               // words per K (or V) stage
#define A3_BYTES (3 * KVW * 2 * 4)             // 55296 bytes -> 2 CTAs/SM

__global__ __launch_bounds__(256, 2) void attn_f16(
    const __half* __restrict__ Q, const __half* __restrict__ K,
    const __half* __restrict__ V, const int* __restrict__ mask,
    __half* __restrict__ ctx)
{
    extern __shared__ __align__(16) uint32_t sh[];
    uint32_t* Kw = sh;
    uint32_t* Vw = sh + 3 * KVW;

    const int q0 = blockIdx.x * 128, h = blockIdx.y, b = blockIdx.z;
    const int t = threadIdx.x, lane = t & 31, warp = t >> 5;
    const int g = lane >> 2, tg = lane & 3;
    const int wbase = warp * 16;
    const int ti = lane >> 3, r8 = lane & 7;
    const int knRow = ((ti >> 1) << 3) + r8;
    const int kCol  = ti & 1;
    const int vRow  = ((ti & 1) << 3) + r8;
    const int vCol  = ti >> 1;

    const uint32_t smK = smaddr(Kw), smV = smaddr(Vw);

    // stage Q through the V region (6912 words >= 4608 needed), extract frags
#pragma unroll
    for (int i = 0; i < 4; i++) {
        int id = t + 256 * i;
        int r = id >> 3, c = id & 7;
        cp16(smV + (uint32_t)(r * 144 + c * 16),
             Q + (size_t)(b * LQ + q0 + r) * HH + h * HD + c * 8);
    }
    cp_commit(); cp_wait0(); __syncthreads();

    uint32_t qf[4][4];
    {
        int r0 = wbase + g, r1 = r0 + 8;
#pragma unroll
        for (int k16 = 0; k16 < 4; k16++) {
            qf[k16][0] = Vw[r0 * 36 + k16 * 8 + tg];
            qf[k16][1] = Vw[r1 * 36 + k16 * 8 + tg];
            qf[k16][2] = Vw[r0 * 36 + k16 * 8 + 4 + tg];
            qf[k16][3] = Vw[r1 * 36 + k16 * 8 + 4 + tg];
        }
    }
    __syncthreads();

    auto loadKV = [&](int s, int k0) {
#pragma unroll
        for (int i = 0; i < 2; i++) {
            int id = t + 256 * i;
            int r = id >> 3, c = id & 7;
            size_t gofs = (size_t)(b * LK + k0 + r) * HH + h * HD + c * 8;
            cp16(smK + (uint32_t)(s * KVW * 4 + r * 144 + c * 16), K + gofs);
            cp16(smV + (uint32_t)(s * KVW * 4 + r * 144 + c * 16), V + gofs);
        }
    };
    loadKV(0, 0);  cp_commit();
    loadKV(1, 64); cp_commit();

    float acc[8][4] = {};
    float m0 = -1e30f, m1 = -1e30f, l0 = 0.f, l1 = 0.f;
    const int* mbase = mask + (size_t)(b * LQ + q0) * LK;
    const int nkt = LK / 64;
    const int r0 = wbase + g, r1 = r0 + 8;

    for (int kt = 0; kt < nkt; kt++) {
        if (kt + 1 < nkt) cp_wait1(); else cp_wait0();
        __syncthreads();
        if (kt + 2 < nkt) { loadKV((kt + 2) % 3, (kt + 2) * 64); cp_commit(); }

        const uint32_t kcB = smK + (uint32_t)((kt % 3) * KVW * 4);
        const uint32_t vcB = smV + (uint32_t)((kt % 3) * KVW * 4);

        int2 mk0[8], mk1[8];
#pragma unroll
        for (int ni = 0; ni < 8; ni++) {
            int c = ni * 8 + tg * 2;
            mk0[ni] = *reinterpret_cast<const int2*>(mbase + (size_t)r0 * LK + kt * 64 + c);
            mk1[ni] = *reinterpret_cast<const int2*>(mbase + (size_t)r1 * LK + kt * 64 + c);
        }

        // S = Q K^T
        float s[8][4] = {};
#pragma unroll
        for (int k16 = 0; k16 < 4; k16++) {
#pragma unroll
            for (int nip = 0; nip < 4; nip++) {
                uint32_t b0, b1, b2, b3;
                uint32_t addr = kcB + (uint32_t)((nip * 16 + knRow) * 144
                                                 + (k16 * 2 + kCol) * 16);
                ldsm4(b0, b1, b2, b3, addr);
                mma16(s[2 * nip], qf[k16][0], qf[k16][1], qf[k16][2], qf[k16][3], b0, b1);
                mma16(s[2 * nip + 1], qf[k16][0], qf[k16][1], qf[k16][2], qf[k16][3], b2, b3);
            }
        }

        // mask + scale, row max
        float mx0 = m0, mx1 = m1;
#pragma unroll
        for (int ni = 0; ni < 8; ni++) {
            s[ni][0] = (mk0[ni].x == 0) ? -1e9f : s[ni][0] * 0.125f;
            s[ni][1] = (mk0[ni].y == 0) ? -1e9f : s[ni][1] * 0.125f;
            s[ni][2] = (mk1[ni].x == 0) ? -1e9f : s[ni][2] * 0.125f;
            s[ni][3] = (mk1[ni].y == 0) ? -1e9f : s[ni][3] * 0.125f;
            mx0 = fmaxf(mx0, fmaxf(s[ni][0], s[ni][1]));
            mx1 = fmaxf(mx1, fmaxf(s[ni][2], s[ni][3]));
        }
        mx0 = fmaxf(mx0, __shfl_xor_sync(0xffffffff, mx0, 1));
        mx0 = fmaxf(mx0, __shfl_xor_sync(0xffffffff, mx0, 2));
        mx1 = fmaxf(mx1, __shfl_xor_sync(0xffffffff, mx1, 1));
        mx1 = fmaxf(mx1, __shfl_xor_sync(0xffffffff, mx1, 2));

        float al0 = __expf(m0 - mx0), al1 = __expf(m1 - mx1);
        float ls0 = 0.f, ls1 = 0.f;
#pragma unroll
        for (int ni = 0; ni < 8; ni++) {
            s[ni][0] = __expf(s[ni][0] - mx0);
            s[ni][1] = __expf(s[ni][1] - mx0);
            s[ni][2] = __expf(s[ni][2] - mx1);
            s[ni][3] = __expf(s[ni][3] - mx1);
            ls0 += s[ni][0] + s[ni][1];
            ls1 += s[ni][2] + s[ni][3];
        }
        ls0 += __shfl_xor_sync(0xffffffff, ls0, 1);
        ls0 += __shfl_xor_sync(0xffffffff, ls0, 2);
        ls1 += __shfl_xor_sync(0xffffffff, ls1, 1);
        ls1 += __shfl_xor_sync(0xffffffff, ls1, 2);
        l0 = l0 * al0 + ls0;  m0 = mx0;
        l1 = l1 * al1 + ls1;  m1 = mx1;

        // rescale accumulator; pack P to fp16 A-fragments (registers only)
        uint32_t pa[4][4];
#pragma unroll
        for (int ni = 0; ni < 8; ni++) {
            acc[ni][0] *= al0; acc[ni][1] *= al0;
            acc[ni][2] *= al1; acc[ni][3] *= al1;
        }
#pragma unroll
        for (int k16 = 0; k16 < 4; k16++) {
            pa[k16][0] = ph2(s[2 * k16][0], s[2 * k16][1]);
            pa[k16][1] = ph2(s[2 * k16][2], s[2 * k16][3]);
            pa[k16][2] = ph2(s[2 * k16 + 1][0], s[2 * k16 + 1][1]);
            pa[k16][3] = ph2(s[2 * k16 + 1][2], s[2 * k16 + 1][3]);
        }

        // O += P @ V
#pragma unroll
        for (int k16 = 0; k16 < 4; k16++) {
#pragma unroll
            for (int nip = 0; nip < 4; nip++) {
                uint32_t b0, b1, b2, b3;
                uint32_t addr = vcB + (uint32_t)((k16 * 16 + vRow) * 144
                                                 + (nip * 2 + vCol) * 16);
                ldsm4t(b0, b1, b2, b3, addr);
                mma16(acc[2 * nip], pa[k16][0], pa[k16][1], pa[k16][2], pa[k16][3], b0, b1);
                mma16(acc[2 * nip + 1], pa[k16][0], pa[k16][1], pa[k16][2], pa[k16][3], b2, b3);
            }
        }
    }

    // epilogue: ctx fp16
    {
        float inv0 = 1.f / l0, inv1 = 1.f / l1;
#pragma unroll
        for (int ni = 0; ni < 8; ni++) {
            int c = ni * 8 + tg * 2;
            size_t o0 = (size_t)(b * LQ + q0 + r0) * HH + h * HD + c;
            size_t o1 = (size_t)(b * LQ + q0 + r1) * HH + h * HD + c;
            *reinterpret_cast<__half2*>(ctx + o0) =
                __floats2half2_rn(acc[ni][0] * inv0, acc[ni][1] * inv0);
            *reinterpret_cast<__half2*>(ctx + o1) =
                __floats2half2_rn(acc[ni][2] * inv1, acc[ni][3] * inv1);
        }
    }
}

// -------------------- LayerNorm --------------------
__device__ __forceinline__ float block_reduce_sum(float v)
{
    __shared__ float red[8];
    __shared__ float tot;
    __syncthreads();
#pragma unroll
    for (int o = 16; o > 0; o >>= 1) v += __shfl_xor_sync(0xffffffff, v, o);
    int w = threadIdx.x >> 5;
    if ((threadIdx.x & 31) == 0) red[w] = v;
    __syncthreads();
    if (threadIdx.x < 32) {
        float r = (threadIdx.x < 8) ? red[threadIdx.x] : 0.f;
#pragma unroll
        for (int o = 4; o > 0; o >>= 1) r += __shfl_xor_sync(0xffffffff, r, o);
        if (threadIdx.x == 0) tot = r;
    }
    __syncthreads();
    return tot;
}

__global__ __launch_bounds__(256) void ln_kernel(
    const float* __restrict__ X, const float* __restrict__ g,
    const float* __restrict__ bta, float* __restrict__ out)
{
    int row = blockIdx.x;
    const float4 x4 = reinterpret_cast<const float4*>(X + (size_t)row * HH)[threadIdx.x];
    float v[4] = {x4.x, x4.y, x4.z, x4.w};
    float s = v[0] + v[1] + v[2] + v[3];
    float mean = block_reduce_sum(s) * (1.f / (float)HH);
    float d2 = 0.f;
#pragma unroll
    for (int j = 0; j < 4; j++) { float d = v[j] - mean; d2 += d * d; }
    float var = block_reduce_sum(d2) * (1.f / (float)HH);
    float rstd = rsqrtf(var + EPS);
    float4 g4 = reinterpret_cast<const float4*>(g)[threadIdx.x];
    float4 b4 = reinterpret_cast<const float4*>(bta)[threadIdx.x];
    float4 o;
    o.x = (v[0] - mean) * rstd * g4.x + b4.x;
    o.y = (v[1] - mean) * rstd * g4.y + b4.y;
    o.z = (v[2] - mean) * rstd * g4.z + b4.z;
    o.w = (v[3] - mean) * rstd * g4.w + b4.w;
    reinterpret_cast<float4*>(out + (size_t)row * HH)[threadIdx.x] = o;
}

// -------------------- launch --------------------
extern "C" void kernel_launch(void* const* d_in, const int* in_sizes, int n_in,
                              void* d_out, int out_size)
{
    const float* query = (const float*)d_in[0];
    const float* key   = (const float*)d_in[1];
    const float* value = (const float*)d_in[2];
    const int*   mask  = (const int*)d_in[3];
    const float* bq = (const float*)d_in[5];
    const float* bk = (const float*)d_in[7];
    const float* bv = (const float*)d_in[9];
    const float* bo = (const float*)d_in[11];
    const float* ln_g = (const float*)d_in[12];
    const float* ln_b = (const float*)d_in[13];
    float* out = (float*)d_out;

    __half *pq16, *pk16, *pv16, *pwq, *pwk, *pwv, *pwo, *pQ16, *pK16, *pV16, *pctx;
    float *pX;
    cudaGetSymbolAddress((void**)&pq16, c_q16);
    cudaGetSymbolAddress((void**)&pk16, c_k16);
    cudaGetSymbolAddress((void**)&pv16, c_v16);
    cudaGetSymbolAddress((void**)&pwq, w16q);
    cudaGetSymbolAddress((void**)&pwk, w16k);
    cudaGetSymbolAddress((void**)&pwv, w16v);
    cudaGetSymbolAddress((void**)&pwo, w16o);
    cudaGetSymbolAddress((void**)&pQ16, g_Q16);
    cudaGetSymbolAddress((void**)&pK16, g_K16);
    cudaGetSymbolAddress((void**)&pV16, g_V16);
    cudaGetSymbolAddress((void**)&pctx, g_ctx16);
    cudaGetSymbolAddress((void**)&pX, g_x);

    cudaFuncSetAttribute(attn_f16,
                         cudaFuncAttributeMaxDynamicSharedMemorySize, A3_BYTES);

    // 1) convert inputs + weights to fp16
    CvtArgs ca;
    ca.src[0] = query; ca.dst[0] = pq16;
    ca.src[1] = key;   ca.dst[1] = pk16;
    ca.src[2] = value; ca.dst[2] = pv16;
    ca.src[3] = (const float*)d_in[4];  ca.dst[3] = pwq;
    ca.src[4] = (const float*)d_in[6];  ca.dst[4] = pwk;
    ca.src[5] = (const float*)d_in[8];  ca.dst[5] = pwv;
    ca.src[6] = (const float*)d_in[10]; ca.dst[6] = pwo;
    int bs[8] = {0, 1024, 3072, 5120, 5632, 6144, 6656, 7168};
    for (int i = 0; i < 8; i++) ca.bstart[i] = bs[i];
    cvt_f16<<<7168, 256>>>(ca);

    // 2) fused Q/K/V projections (fp16 mma)
    GemmArgs qa;
    qa.nseg = 3;
    qa.seg[0] = {pq16, pwq, bq, nullptr, (void*)pQ16, 1, 0};
    qa.seg[1] = {pk16, pwk, bk, nullptr, (void*)pK16, 1, 16};
    qa.seg[2] = {pv16, pwv, bv, nullptr, (void*)pV16, 1, 48};
    gemm_f16<128><<<dim3(HH / 128, 80), 256>>>(qa);

    // 3) attention (3-stage K/V ring)
    attn_f16<<<dim3(LQ / 128, NH, BB), 256, A3_BYTES>>>(pQ16, pK16, pV16, mask, pctx);

    // 4) output projection + residual (64-col tiles -> 256 CTAs)
    GemmArgs oa;
    oa.nseg = 1;
    oa.seg[0] = {pctx, pwo, bo, query, (void*)pX, 0, 0};
    oa.seg[1] = oa.seg[0];
    oa.seg[2] = oa.seg[0];
    gemm_f16<64><<<dim3(HH / 64, 16), 256>>>(oa);

    // 5) layernorm
    ln_kernel<<<BB * LQ, 256>>>(pX, ln_g, ln_b, out);
}

// round 13
// speedup vs baseline: 1.2474x; 1.1167x over previous
#include <cuda_runtime.h>
#include <cuda_fp16.h>
#include <math.h>
#include <stdint.h>

// Problem constants (fixed shapes)
#define BB   2
#define LQ   1024
#define LK   2048
#define HH   1024
#define NH   16
#define HD   64
#define EPS  1e-5f

// -------------------- scratch --------------------
__device__ __align__(256) __half c_q16[BB * LQ * HH];
__device__ __align__(256) __half c_k16[BB * LK * HH];
__device__ __align__(256) __half c_v16[BB * LK * HH];
__device__ __align__(256) __half w16q[HH * HH];
__device__ __align__(256) __half w16k[HH * HH];
__device__ __align__(256) __half w16v[HH * HH];
__device__ __align__(256) __half w16o[HH * HH];
__device__ __align__(256) __half g_Q16[BB * LQ * HH];
__device__ __align__(256) __half g_K16[BB * LK * HH];
__device__ __align__(256) __half g_V16[BB * LK * HH];
__device__ __align__(256) __half g_ctx16[BB * LQ * HH];
__device__ __align__(256) float  g_x[BB * LQ * HH];

// -------------------- helpers --------------------
__device__ __forceinline__ uint32_t smaddr(const void* p) {
    return (uint32_t)__cvta_generic_to_shared(p);
}
__device__ __forceinline__ void cp16(uint32_t dst, const void* src) {
    asm volatile("cp.async.cg.shared.global [%0], [%1], 16;" :: "r"(dst), "l"(src));
}
__device__ __forceinline__ void cp_commit() {
    asm volatile("cp.async.commit_group;");
}
__device__ __forceinline__ void cp_wait0() {
    asm volatile("cp.async.wait_group 0;");
}
__device__ __forceinline__ void mma16(float* c,
    uint32_t a0, uint32_t a1, uint32_t a2, uint32_t a3,
    uint32_t b0, uint32_t b1)
{
    asm volatile(
        "mma.sync.aligned.m16n8k16.row.col.f32.f16.f16.f32 "
        "{%0,%1,%2,%3},{%4,%5,%6,%7},{%8,%9},{%0,%1,%2,%3};"
        : "+f"(c[0]), "+f"(c[1]), "+f"(c[2]), "+f"(c[3])
        : "r"(a0), "r"(a1), "r"(a2), "r"(a3), "r"(b0), "r"(b1));
}
__device__ __forceinline__ void ldsm4(uint32_t& r0, uint32_t& r1, uint32_t& r2,
                                      uint32_t& r3, uint32_t a)
{
    asm volatile("ldmatrix.sync.aligned.m8n8.x4.shared.b16 {%0,%1,%2,%3}, [%4];"
                 : "=r"(r0), "=r"(r1), "=r"(r2), "=r"(r3) : "r"(a));
}
__device__ __forceinline__ void ldsm4t(uint32_t& r0, uint32_t& r1, uint32_t& r2,
                                       uint32_t& r3, uint32_t a)
{
    asm volatile("ldmatrix.sync.aligned.m8n8.x4.trans.shared.b16 {%0,%1,%2,%3}, [%4];"
                 : "=r"(r0), "=r"(r1), "=r"(r2), "=r"(r3) : "r"(a));
}
__device__ __forceinline__ uint32_t ph2(float x, float y) {
    __half2 h = __floats2half2_rn(x, y);
    return *reinterpret_cast<uint32_t*>(&h);
}

// -------------------- fp32 -> fp16 conversion --------------------
struct CvtArgs {
    const float* src[7];
    __half* dst[7];
    int bstart[8];
};

__global__ __launch_bounds__(256) void cvt_f16(CvtArgs a)
{
    int bid = blockIdx.x, s = 0;
#pragma unroll
    for (int i = 1; i < 7; i++) if (bid >= a.bstart[i]) s = i;
    int off = (bid - a.bstart[s]) * 2048 + threadIdx.x * 8;
    float4 v0 = *reinterpret_cast<const float4*>(a.src[s] + off);
    float4 v1 = *reinterpret_cast<const float4*>(a.src[s] + off + 4);
    __half2 h0 = __floats2half2_rn(v0.x, v0.y);
    __half2 h1 = __floats2half2_rn(v0.z, v0.w);
    __half2 h2 = __floats2half2_rn(v1.x, v1.y);
    __half2 h3 = __floats2half2_rn(v1.z, v1.w);
    uint4 o;
    o.x = *reinterpret_cast<uint32_t*>(&h0);
    o.y = *reinterpret_cast<uint32_t*>(&h1);
    o.z = *reinterpret_cast<uint32_t*>(&h2);
    o.w = *reinterpret_cast<uint32_t*>(&h3);
    *reinterpret_cast<uint4*>(a.dst[s] + off) = o;
}

// -------------------- fp16 GEMM v2: BK=64, ldmatrix fragments -------------------
// CTA tile 128(M) x NT(N), BK=64, double-buffered cp.async, 256 threads =
// 8 warps (4M x 2N). 144B row stride (ldsm conflict-free). 2 CTAs/SM.
struct GemmSeg {
    const __half* A; const __half* W;
    const float* bias; const float* residual;
    void* C; int outHalf; int tileStart;
};
struct GemmArgs { GemmSeg seg[3]; int nseg; };

template<int NT>
__global__ __launch_bounds__(256, 2) void gemm_f16(GemmArgs ga)
{
    constexpr int NI = NT / 16;                 // mma n-steps per warp
    constexpr int ASTG = 128 * 36;              // words per A stage
    constexpr int BSTG = NT * 36;               // words per B stage
    extern __shared__ __align__(16) uint32_t dsm[];
    const uint32_t smA = smaddr(dsm);
    const uint32_t smB = smA + 2 * ASTG * 4;

    const int y = blockIdx.y;
    int si = 0;
#pragma unroll
    for (int i = 1; i < 3; i++) if (i < ga.nseg && y >= ga.seg[i].tileStart) si = i;
    const GemmSeg sg = ga.seg[si];

    const int t = threadIdx.x, lane = t & 31, warp = t >> 5;
    const int g = lane >> 2, tg = lane & 3;
    const int wm = warp & 3, wn = warp >> 2;
    const int rowBase = (y - sg.tileStart) * 128, colBase = blockIdx.x * NT;
    const int ti = lane >> 3, r8 = lane & 7;
    const int aRow = ((ti & 1) << 3) + r8, aCol = ti >> 1;   // A ldsm (non-trans)
    const int bRow = ((ti >> 1) << 3) + r8, bCol = ti & 1;   // B ldsm (non-trans)

    auto loadStage = [&](int buf, int k0) {
#pragma unroll
        for (int i = 0; i < 4; i++) {            // A: 128 rows x 8 chunks
            int id = t + 256 * i;
            int r = id >> 3, c = id & 7;
            cp16(smA + (uint32_t)(buf * ASTG * 4 + r * 144 + c * 16),
                 sg.A + (size_t)(rowBase + r) * HH + k0 + c * 8);
        }
#pragma unroll
        for (int i = 0; i < NT / 32; i++) {      // B: NT rows x 8 chunks
            int id = t + 256 * i;
            int r = id >> 3, c = id & 7;
            cp16(smB + (uint32_t)(buf * BSTG * 4 + r * 144 + c * 16),
                 sg.W + (size_t)(colBase + r) * HH + k0 + c * 8);
        }
    };

    loadStage(0, 0);
    cp_commit();

    float acc[2][NI][4] = {};
    const int nst = HH / 64;

    for (int s = 0; s < nst; s++) {
        cp_wait0();
        __syncthreads();
        if (s + 1 < nst) { loadStage((s + 1) & 1, (s + 1) * 64); cp_commit(); }

        const uint32_t aBase = smA + (uint32_t)((s & 1) * ASTG * 4);
        const uint32_t bBase = smB + (uint32_t)((s & 1) * BSTG * 4);

#pragma unroll
        for (int k16 = 0; k16 < 4; k16++) {
            uint32_t a[2][4];
#pragma unroll
            for (int mi = 0; mi < 2; mi++) {
                ldsm4(a[mi][0], a[mi][1], a[mi][2], a[mi][3],
                      aBase + (uint32_t)((wm * 32 + mi * 16 + aRow) * 144
                                         + (k16 * 2 + aCol) * 16));
            }
#pragma unroll
            for (int nip = 0; nip < NI / 2; nip++) {
                uint32_t b0, b1, b2, b3;
                ldsm4(b0, b1, b2, b3,
                      bBase + (uint32_t)((wn * (NT / 2) + nip * 16 + bRow) * 144
                                         + (k16 * 2 + bCol) * 16));
                mma16(acc[0][2 * nip],     a[0][0], a[0][1], a[0][2], a[0][3], b0, b1);
                mma16(acc[0][2 * nip + 1], a[0][0], a[0][1], a[0][2], a[0][3], b2, b3);
                mma16(acc[1][2 * nip],     a[1][0], a[1][1], a[1][2], a[1][3], b0, b1);
                mma16(acc[1][2 * nip + 1], a[1][0], a[1][1], a[1][2], a[1][3], b2, b3);
            }
        }
    }

#pragma unroll
    for (int mi = 0; mi < 2; mi++) {
#pragma unroll
        for (int ni = 0; ni < NI; ni++) {
            int r = rowBase + wm * 32 + mi * 16 + g;
            int c = colBase + wn * (NT / 2) + ni * 8 + tg * 2;
            float b0 = sg.bias[c], b1 = sg.bias[c + 1];
            float v0 = acc[mi][ni][0] + b0, v1 = acc[mi][ni][1] + b1;
            float v2 = acc[mi][ni][2] + b0, v3 = acc[mi][ni][3] + b1;
            if (sg.outHalf) {
                __half* Ch = (__half*)sg.C;
                *reinterpret_cast<__half2*>(Ch + (size_t)r * HH + c) = __floats2half2_rn(v0, v1);
                *reinterpret_cast<__half2*>(Ch + (size_t)(r + 8) * HH + c) = __floats2half2_rn(v2, v3);
            } else {
                float* Cf = (float*)sg.C;
                if (sg.residual) {
                    float2 r0 = *reinterpret_cast<const float2*>(sg.residual + (size_t)r * HH + c);
                    float2 r1 = *reinterpret_cast<const float2*>(sg.residual + (size_t)(r + 8) * HH + c);
                    v0 += r0.x; v1 += r0.y; v2 += r1.x; v3 += r1.y;
                }
                *reinterpret_cast<float2*>(Cf + (size_t)r * HH + c) = make_float2(v0, v1);
                *reinterpret_cast<float2*>(Cf + (size_t)(r + 8) * HH + c) = make_float2(v2, v3);
            }
        }
    }
}

#define G128_SMEM (2 * (128 * 36 + 128 * 36) * 4)   // 73728
#define G64_SMEM  (2 * (128 * 36 + 64 * 36) * 4)    // 55296

// -------------------- Flash attention v8 (Round-10 best, unchanged) ------------
#define K16W 2304
#define V16W 2304
#define A3_BYTES ((2 * K16W + 2 * V16W) * 4)   // 36864 bytes -> 2 CTAs/SM

__global__ __launch_bounds__(256, 2) void attn_f16(
    const __half* __restrict__ Q, const __half* __restrict__ K,
    const __half* __restrict__ V, const int* __restrict__ mask,
    __half* __restrict__ ctx)
{
    extern __shared__ __align__(16) uint32_t sh[];
    uint32_t* Kw = sh;
    uint32_t* Vw = sh + 2 * K16W;

    const int q0 = blockIdx.x * 128, h = blockIdx.y, b = blockIdx.z;
    const int t = threadIdx.x, lane = t & 31, warp = t >> 5;
    const int g = lane >> 2, tg = lane & 3;
    const int wbase = warp * 16;
    const int ti = lane >> 3, r8 = lane & 7;
    const int knRow = ((ti >> 1) << 3) + r8;
    const int kCol  = ti & 1;
    const int vRow  = ((ti & 1) << 3) + r8;
    const int vCol  = ti >> 1;

    const uint32_t smK = smaddr(Kw), smV = smaddr(Vw);

    // stage Q through the V region, extract fragments
#pragma unroll
    for (int i = 0; i < 4; i++) {
        int id = t + 256 * i;
        int r = id >> 3, c = id & 7;
        cp16(smV + (uint32_t)(r * 144 + c * 16),
             Q + (size_t)(b * LQ + q0 + r) * HH + h * HD + c * 8);
    }
    cp_commit(); cp_wait0(); __syncthreads();

    uint32_t qf[4][4];
    {
        int r0 = wbase + g, r1 = r0 + 8;
#pragma unroll
        for (int k16 = 0; k16 < 4; k16++) {
            qf[k16][0] = Vw[r0 * 36 + k16 * 8 + tg];
            qf[k16][1] = Vw[r1 * 36 + k16 * 8 + tg];
            qf[k16][2] = Vw[r0 * 36 + k16 * 8 + 4 + tg];
            qf[k16][3] = Vw[r1 * 36 + k16 * 8 + 4 + tg];
        }
    }
    __syncthreads();

    auto loadKV = [&](int s, int k0) {
#pragma unroll
        for (int i = 0; i < 2; i++) {
            int id = t + 256 * i;
            int r = id >> 3, c = id & 7;
            size_t gofs = (size_t)(b * LK + k0 + r) * HH + h * HD + c * 8;
            cp16(smK + (uint32_t)(s * K16W * 4 + r * 144 + c * 16), K + gofs);
            cp16(smV + (uint32_t)(s * V16W * 4 + r * 144 + c * 16), V + gofs);
        }
    };
    loadKV(0, 0);
    cp_commit(); cp_wait0(); __syncthreads();

    float acc[8][4] = {};
    float m0 = -1e30f, m1 = -1e30f, l0 = 0.f, l1 = 0.f;
    const int* mbase = mask + (size_t)(b * LQ + q0) * LK;
    const int nkt = LK / 64;
    const int r0 = wbase + g, r1 = r0 + 8;

    for (int kt = 0; kt < nkt; kt++) {
        if (kt + 1 < nkt) { loadKV((kt + 1) & 1, (kt + 1) * 64); cp_commit(); }

        const uint32_t kcB = smK + (uint32_t)((kt & 1) * K16W * 4);
        const uint32_t vcB = smV + (uint32_t)((kt & 1) * V16W * 4);

        int2 mk0[8], mk1[8];
#pragma unroll
        for (int ni = 0; ni < 8; ni++) {
            int c = ni * 8 + tg * 2;
            mk0[ni] = *reinterpret_cast<const int2*>(mbase + (size_t)r0 * LK + kt * 64 + c);
            mk1[ni] = *reinterpret_cast<const int2*>(mbase + (size_t)r1 * LK + kt * 64 + c);
        }

        // S = Q K^T
        float s[8][4] = {};
#pragma unroll
        for (int k16 = 0; k16 < 4; k16++) {
#pragma unroll
            for (int nip = 0; nip < 4; nip++) {
                uint32_t b0, b1, b2, b3;
                uint32_t addr = kcB + (uint32_t)((nip * 16 + knRow) * 144
                                                 + (k16 * 2 + kCol) * 16);
                ldsm4(b0, b1, b2, b3, addr);
                mma16(s[2 * nip], qf[k16][0], qf[k16][1], qf[k16][2], qf[k16][3], b0, b1);
                mma16(s[2 * nip + 1], qf[k16][0], qf[k16][1], qf[k16][2], qf[k16][3], b2, b3);
            }
        }

        // mask + scale, row max
        float mx0 = m0, mx1 = m1;
#pragma unroll
        for (int ni = 0; ni < 8; ni++) {
            s[ni][0] = (mk0[ni].x == 0) ? -1e9f : s[ni][0] * 0.125f;
            s[ni][1] = (mk0[ni].y == 0) ? -1e9f : s[ni][1] * 0.125f;
            s[ni][2] = (mk1[ni].x == 0) ? -1e9f : s[ni][2] * 0.125f;
            s[ni][3] = (mk1[ni].y == 0) ? -1e9f : s[ni][3] * 0.125f;
            mx0 = fmaxf(mx0, fmaxf(s[ni][0], s[ni][1]));
            mx1 = fmaxf(mx1, fmaxf(s[ni][2], s[ni][3]));
        }
        mx0 = fmaxf(mx0, __shfl_xor_sync(0xffffffff, mx0, 1));
        mx0 = fmaxf(mx0, __shfl_xor_sync(0xffffffff, mx0, 2));
        mx1 = fmaxf(mx1, __shfl_xor_sync(0xffffffff, mx1, 1));
        mx1 = fmaxf(mx1, __shfl_xor_sync(0xffffffff, mx1, 2));

        float al0 = __expf(m0 - mx0), al1 = __expf(m1 - mx1);
        float ls0 = 0.f, ls1 = 0.f;
#pragma unroll
        for (int ni = 0; ni < 8; ni++) {
            s[ni][0] = __expf(s[ni][0] - mx0);
            s[ni][1] = __expf(s[ni][1] - mx0);
            s[ni][2] = __expf(s[ni][2] - mx1);
            s[ni][3] = __expf(s[ni][3] - mx1);
            ls0 += s[ni][0] + s[ni][1];
            ls1 += s[ni][2] + s[ni][3];
        }
        ls0 += __shfl_xor_sync(0xffffffff, ls0, 1);
        ls0 += __shfl_xor_sync(0xffffffff, ls0, 2);
        ls1 += __shfl_xor_sync(0xffffffff, ls1, 1);
        ls1 += __shfl_xor_sync(0xffffffff, ls1, 2);
        l0 = l0 * al0 + ls0;  m0 = mx0;
        l1 = l1 * al1 + ls1;  m1 = mx1;

        // rescale accumulator; pack P to fp16 A-fragments (registers only)
        uint32_t pa[4][4];
#pragma unroll
        for (int ni = 0; ni < 8; ni++) {
            acc[ni][0] *= al0; acc[ni][1] *= al0;
            acc[ni][2] *= al1; acc[ni][3] *= al1;
        }
#pragma unroll
        for (int k16 = 0; k16 < 4; k16++) {
            pa[k16][0] = ph2(s[2 * k16][0], s[2 * k16][1]);
            pa[k16][1] = ph2(s[2 * k16][2], s[2 * k16][3]);
            pa[k16][2] = ph2(s[2 * k16 + 1][0], s[2 * k16 + 1][1]);
            pa[k16][3] = ph2(s[2 * k16 + 1][2], s[2 * k16 + 1][3]);
        }

        // O += P @ V
#pragma unroll
        for (int k16 = 0; k16 < 4; k16++) {
#pragma unroll
            for (int nip = 0; nip < 4; nip++) {
                uint32_t b0, b1, b2, b3;
                uint32_t addr = vcB + (uint32_t)((k16 * 16 + vRow) * 144
                                                 + (nip * 2 + vCol) * 16);
                ldsm4t(b0, b1, b2, b3, addr);
                mma16(acc[2 * nip], pa[k16][0], pa[k16][1], pa[k16][2], pa[k16][3], b0, b1);
                mma16(acc[2 * nip + 1], pa[k16][0], pa[k16][1], pa[k16][2], pa[k16][3], b2, b3);
            }
        }

        cp_wait0();
        __syncthreads();
    }

    // epilogue: ctx fp16
    {
        float inv0 = 1.f / l0, inv1 = 1.f / l1;
#pragma unroll
        for (int ni = 0; ni < 8; ni++) {
            int c = ni * 8 + tg * 2;
            size_t o0 = (size_t)(b * LQ + q0 + r0) * HH + h * HD + c;
            size_t o1 = (size_t)(b * LQ + q0 + r1) * HH + h * HD + c;
            *reinterpret_cast<__half2*>(ctx + o0) =
                __floats2half2_rn(acc[ni][0] * inv0, acc[ni][1] * inv0);
            *reinterpret_cast<__half2*>(ctx + o1) =
                __floats2half2_rn(acc[ni][2] * inv1, acc[ni][3] * inv1);
        }
    }
}

// -------------------- LayerNorm --------------------
__device__ __forceinline__ float block_reduce_sum(float v)
{
    __shared__ float red[8];
    __shared__ float tot;
    __syncthreads();
#pragma unroll
    for (int o = 16; o > 0; o >>= 1) v += __shfl_xor_sync(0xffffffff, v, o);
    int w = threadIdx.x >> 5;
    if ((threadIdx.x & 31) == 0) red[w] = v;
    __syncthreads();
    if (threadIdx.x < 32) {
        float r = (threadIdx.x < 8) ? red[threadIdx.x] : 0.f;
#pragma unroll
        for (int o = 4; o > 0; o >>= 1) r += __shfl_xor_sync(0xffffffff, r, o);
        if (threadIdx.x == 0) tot = r;
    }
    __syncthreads();
    return tot;
}

__global__ __launch_bounds__(256) void ln_kernel(
    const float* __restrict__ X, const float* __restrict__ g,
    const float* __restrict__ bta, float* __restrict__ out)
{
    int row = blockIdx.x;
    const float4 x4 = reinterpret_cast<const float4*>(X + (size_t)row * HH)[threadIdx.x];
    float v[4] = {x4.x, x4.y, x4.z, x4.w};
    float s = v[0] + v[1] + v[2] + v[3];
    float mean = block_reduce_sum(s) * (1.f / (float)HH);
    float d2 = 0.f;
#pragma unroll
    for (int j = 0; j < 4; j++) { float d = v[j] - mean; d2 += d * d; }
    float var = block_reduce_sum(d2) * (1.f / (float)HH);
    float rstd = rsqrtf(var + EPS);
    float4 g4 = reinterpret_cast<const float4*>(g)[threadIdx.x];
    float4 b4 = reinterpret_cast<const float4*>(bta)[threadIdx.x];
    float4 o;
    o.x = (v[0] - mean) * rstd * g4.x + b4.x;
    o.y = (v[1] - mean) * rstd * g4.y + b4.y;
    o.z = (v[2] - mean) * rstd * g4.z + b4.z;
    o.w = (v[3] - mean) * rstd * g4.w + b4.w;
    reinterpret_cast<float4*>(out + (size_t)row * HH)[threadIdx.x] = o;
}

// -------------------- launch --------------------
extern "C" void kernel_launch(void* const* d_in, const int* in_sizes, int n_in,
                              void* d_out, int out_size)
{
    const float* query = (const float*)d_in[0];
    const float* key   = (const float*)d_in[1];
    const float* value = (const float*)d_in[2];
    const int*   mask  = (const int*)d_in[3];
    const float* bq = (const float*)d_in[5];
    const float* bk = (const float*)d_in[7];
    const float* bv = (const float*)d_in[9];
    const float* bo = (const float*)d_in[11];
    const float* ln_g = (const float*)d_in[12];
    const float* ln_b = (const float*)d_in[13];
    float* out = (float*)d_out;

    __half *pq16, *pk16, *pv16, *pwq, *pwk, *pwv, *pwo, *pQ16, *pK16, *pV16, *pctx;
    float *pX;
    cudaGetSymbolAddress((void**)&pq16, c_q16);
    cudaGetSymbolAddress((void**)&pk16, c_k16);
    cudaGetSymbolAddress((void**)&pv16, c_v16);
    cudaGetSymbolAddress((void**)&pwq, w16q);
    cudaGetSymbolAddress((void**)&pwk, w16k);
    cudaGetSymbolAddress((void**)&pwv, w16v);
    cudaGetSymbolAddress((void**)&pwo, w16o);
    cudaGetSymbolAddress((void**)&pQ16, g_Q16);
    cudaGetSymbolAddress((void**)&pK16, g_K16);
    cudaGetSymbolAddress((void**)&pV16, g_V16);
    cudaGetSymbolAddress((void**)&pctx, g_ctx16);
    cudaGetSymbolAddress((void**)&pX, g_x);

    cudaFuncSetAttribute(attn_f16,
                         cudaFuncAttributeMaxDynamicSharedMemorySize, A3_BYTES);
    cudaFuncSetAttribute(gemm_f16<128>,
                         cudaFuncAttributeMaxDynamicSharedMemorySize, G128_SMEM);
    cudaFuncSetAttribute(gemm_f16<64>,
                         cudaFuncAttributeMaxDynamicSharedMemorySize, G64_SMEM);

    // 1) convert inputs + weights to fp16
    CvtArgs ca;
    ca.src[0] = query; ca.dst[0] = pq16;
    ca.src[1] = key;   ca.dst[1] = pk16;
    ca.src[2] = value; ca.dst[2] = pv16;
    ca.src[3] = (const float*)d_in[4];  ca.dst[3] = pwq;
    ca.src[4] = (const float*)d_in[6];  ca.dst[4] = pwk;
    ca.src[5] = (const float*)d_in[8];  ca.dst[5] = pwv;
    ca.src[6] = (const float*)d_in[10]; ca.dst[6] = pwo;
    int bs[8] = {0, 1024, 3072, 5120, 5632, 6144, 6656, 7168};
    for (int i = 0; i < 8; i++) ca.bstart[i] = bs[i];
    cvt_f16<<<7168, 256>>>(ca);

    // 2) fused Q/K/V projections (fp16 mma, BK=64, ldsm)
    GemmArgs qa;
    qa.nseg = 3;
    qa.seg[0] = {pq16, pwq, bq, nullptr, (void*)pQ16, 1, 0};
    qa.seg[1] = {pk16, pwk, bk, nullptr, (void*)pK16, 1, 16};
    qa.seg[2] = {pv16, pwv, bv, nullptr, (void*)pV16, 1, 48};
    gemm_f16<128><<<dim3(HH / 128, 80), 256, G128_SMEM>>>(qa);

    // 3) attention (Round-10 best)
    attn_f16<<<dim3(LQ / 128, NH, BB), 256, A3_BYTES>>>(pQ16, pK16, pV16, mask, pctx);

    // 4) output projection + residual (64-col tiles -> 256 CTAs)
    GemmArgs oa;
    oa.nseg = 1;
    oa.seg[0] = {pctx, pwo, bo, query, (void*)pX, 0, 0};
    oa.seg[1] = oa.seg[0];
    oa.seg[2] = oa.seg[0];
    gemm_f16<64><<<dim3(HH / 64, 16), 256, G64_SMEM>>>(oa);

    // 5) layernorm
    ln_kernel<<<BB * LQ, 256>>>(pX, ln_g, ln_b, out);
}

// round 14
// speedup vs baseline: 1.3031x; 1.0447x over previous
#include <cuda_runtime.h>
#include <cuda_fp16.h>
#include <math.h>
#include <stdint.h>

// Problem constants (fixed shapes)
#define BB   2
#define LQ   1024
#define LK   2048
#define HH   1024
#define NH   16
#define HD   64
#define EPS  1e-5f

// -------------------- scratch --------------------
__device__ __align__(256) __half c_q16[BB * LQ * HH];
__device__ __align__(256) __half c_k16[BB * LK * HH];
__device__ __align__(256) __half c_v16[BB * LK * HH];
__device__ __align__(256) __half w16q[HH * HH];
__device__ __align__(256) __half w16k[HH * HH];
__device__ __align__(256) __half w16v[HH * HH];
__device__ __align__(256) __half w16o[HH * HH];
__device__ __align__(256) __half g_Q16[BB * LQ * HH];
__device__ __align__(256) __half g_K16[BB * LK * HH];
__device__ __align__(256) __half g_V16[BB * LK * HH];
__device__ __align__(256) __half g_ctx16[BB * LQ * HH];
__device__ __align__(256) float  g_x[BB * LQ * HH];
__device__ __align__(256) uint32_t g_mmask[BB * LQ * LK / 32];   // packed mask bits

// -------------------- helpers --------------------
__device__ __forceinline__ uint32_t smaddr(const void* p) {
    return (uint32_t)__cvta_generic_to_shared(p);
}
__device__ __forceinline__ void cp16(uint32_t dst, const void* src) {
    asm volatile("cp.async.cg.shared.global [%0], [%1], 16;" :: "r"(dst), "l"(src));
}
__device__ __forceinline__ void cp_commit() {
    asm volatile("cp.async.commit_group;");
}
__device__ __forceinline__ void cp_wait0() {
    asm volatile("cp.async.wait_group 0;");
}
__device__ __forceinline__ void cp_wait1() {
    asm volatile("cp.async.wait_group 1;");
}
__device__ __forceinline__ void mma16(float* c,
    uint32_t a0, uint32_t a1, uint32_t a2, uint32_t a3,
    uint32_t b0, uint32_t b1)
{
    asm volatile(
        "mma.sync.aligned.m16n8k16.row.col.f32.f16.f16.f32 "
        "{%0,%1,%2,%3},{%4,%5,%6,%7},{%8,%9},{%0,%1,%2,%3};"
        : "+f"(c[0]), "+f"(c[1]), "+f"(c[2]), "+f"(c[3])
        : "r"(a0), "r"(a1), "r"(a2), "r"(a3), "r"(b0), "r"(b1));
}
__device__ __forceinline__ void ldsm4(uint32_t& r0, uint32_t& r1, uint32_t& r2,
                                      uint32_t& r3, uint32_t a)
{
    asm volatile("ldmatrix.sync.aligned.m8n8.x4.shared.b16 {%0,%1,%2,%3}, [%4];"
                 : "=r"(r0), "=r"(r1), "=r"(r2), "=r"(r3) : "r"(a));
}
__device__ __forceinline__ void ldsm4t(uint32_t& r0, uint32_t& r1, uint32_t& r2,
                                       uint32_t& r3, uint32_t a)
{
    asm volatile("ldmatrix.sync.aligned.m8n8.x4.trans.shared.b16 {%0,%1,%2,%3}, [%4];"
                 : "=r"(r0), "=r"(r1), "=r"(r2), "=r"(r3) : "r"(a));
}
__device__ __forceinline__ uint32_t ph2(float x, float y) {
    __half2 h = __floats2half2_rn(x, y);
    return *reinterpret_cast<uint32_t*>(&h);
}

// -------------------- fp32 -> fp16 conversion --------------------
struct CvtArgs {
    const float* src[7];
    __half* dst[7];
    int bstart[8];
};

__global__ __launch_bounds__(256) void cvt_f16(CvtArgs a)
{
    int bid = blockIdx.x, s = 0;
#pragma unroll
    for (int i = 1; i < 7; i++) if (bid >= a.bstart[i]) s = i;
    int off = (bid - a.bstart[s]) * 2048 + threadIdx.x * 8;
    float4 v0 = *reinterpret_cast<const float4*>(a.src[s] + off);
    float4 v1 = *reinterpret_cast<const float4*>(a.src[s] + off + 4);
    __half2 h0 = __floats2half2_rn(v0.x, v0.y);
    __half2 h1 = __floats2half2_rn(v0.z, v0.w);
    __half2 h2 = __floats2half2_rn(v1.x, v1.y);
    __half2 h3 = __floats2half2_rn(v1.z, v1.w);
    uint4 o;
    o.x = *reinterpret_cast<uint32_t*>(&h0);
    o.y = *reinterpret_cast<uint32_t*>(&h1);
    o.z = *reinterpret_cast<uint32_t*>(&h2);
    o.w = *reinterpret_cast<uint32_t*>(&h3);
    *reinterpret_cast<uint4*>(a.dst[s] + off) = o;
}

// -------------------- mask bit-packing (warp ballot, coalesced) ----------------
__global__ __launch_bounds__(256) void mask_pack(
    const int* __restrict__ mask, uint32_t* __restrict__ mp)
{
    int warpG = (blockIdx.x * 256 + threadIdx.x) >> 5;
    int lane = threadIdx.x & 31;
    size_t base = (size_t)warpG * 1024;
    uint32_t myw = 0;
#pragma unroll
    for (int i = 0; i < 32; i++) {
        int v = mask[base + i * 32 + lane];
        uint32_t bl = __ballot_sync(0xffffffff, v != 0);
        if (lane == i) myw = bl;
    }
    mp[(size_t)warpG * 32 + lane] = myw;
}

// -------------------- fp16 GEMM v3: BK=64, ldsm, 3-stage, smem bias ------------
struct GemmSeg {
    const __half* A; const __half* W;
    const float* bias; const float* residual;
    void* C; int outHalf; int tileStart;
};
struct GemmArgs { GemmSeg seg[3]; int nseg; };

template<int NT>
__global__ __launch_bounds__(256, 2) void gemm_f16(GemmArgs ga)
{
    constexpr int NI = NT / 16;
    constexpr int ASTG = 128 * 36;              // words per A stage
    constexpr int BSTG = NT * 36;               // words per B stage
    extern __shared__ __align__(16) uint32_t dsm[];
    const uint32_t smA = smaddr(dsm);
    const uint32_t smB = smA + 3 * ASTG * 4;
    float* biasSm = reinterpret_cast<float*>(dsm + 3 * (ASTG + BSTG));

    const int y = blockIdx.y;
    int si = 0;
#pragma unroll
    for (int i = 1; i < 3; i++) if (i < ga.nseg && y >= ga.seg[i].tileStart) si = i;
    const GemmSeg sg = ga.seg[si];

    const int t = threadIdx.x, lane = t & 31, warp = t >> 5;
    const int g = lane >> 2, tg = lane & 3;
    const int wm = warp & 3, wn = warp >> 2;
    const int rowBase = (y - sg.tileStart) * 128, colBase = blockIdx.x * NT;
    const int ti = lane >> 3, r8 = lane & 7;
    const int aRow = ((ti & 1) << 3) + r8, aCol = ti >> 1;
    const int bRow = ((ti >> 1) << 3) + r8, bCol = ti & 1;

    // prologue: bias tile -> smem (consumed in epilogue, no LDG chain there)
    if (t < NT / 4)
        reinterpret_cast<float4*>(biasSm)[t] =
            reinterpret_cast<const float4*>(sg.bias + colBase)[t];

    auto loadStage = [&](int buf, int k0) {
#pragma unroll
        for (int i = 0; i < 4; i++) {
            int id = t + 256 * i;
            int r = id >> 3, c = id & 7;
            cp16(smA + (uint32_t)(buf * ASTG * 4 + r * 144 + c * 16),
                 sg.A + (size_t)(rowBase + r) * HH + k0 + c * 8);
        }
#pragma unroll
        for (int i = 0; i < NT / 32; i++) {
            int id = t + 256 * i;
            int r = id >> 3, c = id & 7;
            cp16(smB + (uint32_t)(buf * BSTG * 4 + r * 144 + c * 16),
                 sg.W + (size_t)(colBase + r) * HH + k0 + c * 8);
        }
    };

    loadStage(0, 0);  cp_commit();
    loadStage(1, 64); cp_commit();

    float acc[2][NI][4] = {};
    const int nst = HH / 64;

    for (int s = 0; s < nst; s++) {
        if (s + 1 < nst) cp_wait1(); else cp_wait0();
        __syncthreads();
        if (s + 2 < nst) { loadStage((s + 2) % 3, (s + 2) * 64); cp_commit(); }

        const uint32_t aBase = smA + (uint32_t)((s % 3) * ASTG * 4);
        const uint32_t bBase = smB + (uint32_t)((s % 3) * BSTG * 4);

#pragma unroll
        for (int k16 = 0; k16 < 4; k16++) {
            uint32_t a[2][4];
#pragma unroll
            for (int mi = 0; mi < 2; mi++) {
                ldsm4(a[mi][0], a[mi][1], a[mi][2], a[mi][3],
                      aBase + (uint32_t)((wm * 32 + mi * 16 + aRow) * 144
                                         + (k16 * 2 + aCol) * 16));
            }
#pragma unroll
            for (int nip = 0; nip < NI / 2; nip++) {
                uint32_t b0, b1, b2, b3;
                ldsm4(b0, b1, b2, b3,
                      bBase + (uint32_t)((wn * (NT / 2) + nip * 16 + bRow) * 144
                                         + (k16 * 2 + bCol) * 16));
                mma16(acc[0][2 * nip],     a[0][0], a[0][1], a[0][2], a[0][3], b0, b1);
                mma16(acc[0][2 * nip + 1], a[0][0], a[0][1], a[0][2], a[0][3], b2, b3);
                mma16(acc[1][2 * nip],     a[1][0], a[1][1], a[1][2], a[1][3], b0, b1);
                mma16(acc[1][2 * nip + 1], a[1][0], a[1][1], a[1][2], a[1][3], b2, b3);
            }
        }
    }

#pragma unroll
    for (int mi = 0; mi < 2; mi++) {
#pragma unroll
        for (int ni = 0; ni < NI; ni++) {
            int r = rowBase + wm * 32 + mi * 16 + g;
            int cl = wn * (NT / 2) + ni * 8 + tg * 2;
            int c = colBase + cl;
            float b0 = biasSm[cl], b1 = biasSm[cl + 1];
            float v0 = acc[mi][ni][0] + b0, v1 = acc[mi][ni][1] + b1;
            float v2 = acc[mi][ni][2] + b0, v3 = acc[mi][ni][3] + b1;
            if (sg.outHalf) {
                __half* Ch = (__half*)sg.C;
                *reinterpret_cast<__half2*>(Ch + (size_t)r * HH + c) = __floats2half2_rn(v0, v1);
                *reinterpret_cast<__half2*>(Ch + (size_t)(r + 8) * HH + c) = __floats2half2_rn(v2, v3);
            } else {
                float* Cf = (float*)sg.C;
                if (sg.residual) {
                    float2 r0 = *reinterpret_cast<const float2*>(sg.residual + (size_t)r * HH + c);
                    float2 r1 = *reinterpret_cast<const float2*>(sg.residual + (size_t)(r + 8) * HH + c);
                    v0 += r0.x; v1 += r0.y; v2 += r1.x; v3 += r1.y;
                }
                *reinterpret_cast<float2*>(Cf + (size_t)r * HH + c) = make_float2(v0, v1);
                *reinterpret_cast<float2*>(Cf + (size_t)(r + 8) * HH + c) = make_float2(v2, v3);
            }
        }
    }
}

#define G128_SMEM (3 * (128 * 36 + 128 * 36) * 4 + 128 * 4)   // 111104
#define G64_SMEM  (3 * (128 * 36 + 64 * 36) * 4 + 64 * 4)     // 83200

// -------------------- Flash attention v10: packed mask bits --------------------
#define K16W 2304
#define V16W 2304
#define A3_BYTES ((2 * K16W + 2 * V16W) * 4)   // 36864 bytes -> 2 CTAs/SM

__global__ __launch_bounds__(256, 2) void attn_f16(
    const __half* __restrict__ Q, const __half* __restrict__ K,
    const __half* __restrict__ V, const uint32_t* __restrict__ mp,
    __half* __restrict__ ctx)
{
    extern __shared__ __align__(16) uint32_t sh[];
    uint32_t* Kw = sh;
    uint32_t* Vw = sh + 2 * K16W;

    const int q0 = blockIdx.x * 128, h = blockIdx.y, b = blockIdx.z;
    const int t = threadIdx.x, lane = t & 31, warp = t >> 5;
    const int g = lane >> 2, tg = lane & 3;
    const int wbase = warp * 16;
    const int ti = lane >> 3, r8 = lane & 7;
    const int knRow = ((ti >> 1) << 3) + r8;
    const int kCol  = ti & 1;
    const int vRow  = ((ti & 1) << 3) + r8;
    const int vCol  = ti >> 1;

    const uint32_t smK = smaddr(Kw), smV = smaddr(Vw);

    // stage Q through the V region, extract fragments
#pragma unroll
    for (int i = 0; i < 4; i++) {
        int id = t + 256 * i;
        int r = id >> 3, c = id & 7;
        cp16(smV + (uint32_t)(r * 144 + c * 16),
             Q + (size_t)(b * LQ + q0 + r) * HH + h * HD + c * 8);
    }
    cp_commit(); cp_wait0(); __syncthreads();

    uint32_t qf[4][4];
    {
        int r0 = wbase + g, r1 = r0 + 8;
#pragma unroll
        for (int k16 = 0; k16 < 4; k16++) {
            qf[k16][0] = Vw[r0 * 36 + k16 * 8 + tg];
            qf[k16][1] = Vw[r1 * 36 + k16 * 8 + tg];
            qf[k16][2] = Vw[r0 * 36 + k16 * 8 + 4 + tg];
            qf[k16][3] = Vw[r1 * 36 + k16 * 8 + 4 + tg];
        }
    }
    __syncthreads();

    auto loadKV = [&](int s, int k0) {
#pragma unroll
        for (int i = 0; i < 2; i++) {
            int id = t + 256 * i;
            int r = id >> 3, c = id & 7;
            size_t gofs = (size_t)(b * LK + k0 + r) * HH + h * HD + c * 8;
            cp16(smK + (uint32_t)(s * K16W * 4 + r * 144 + c * 16), K + gofs);
            cp16(smV + (uint32_t)(s * V16W * 4 + r * 144 + c * 16), V + gofs);
        }
    };
    loadKV(0, 0);
    cp_commit(); cp_wait0(); __syncthreads();

    float acc[8][4] = {};
    float m0 = -1e30f, m1 = -1e30f, l0 = 0.f, l1 = 0.f;
    const uint32_t* mpb = mp + (size_t)(b * LQ + q0) * (LK / 32);
    const int nkt = LK / 64;
    const int r0 = wbase + g, r1 = r0 + 8;

    for (int kt = 0; kt < nkt; kt++) {
        if (kt + 1 < nkt) { loadKV((kt + 1) & 1, (kt + 1) * 64); cp_commit(); }

        const uint32_t kcB = smK + (uint32_t)((kt & 1) * K16W * 4);
        const uint32_t vcB = smV + (uint32_t)((kt & 1) * V16W * 4);

        // packed mask: 64 bits per row for this tile
        uint2 mw0 = *reinterpret_cast<const uint2*>(mpb + (size_t)r0 * (LK / 32) + kt * 2);
        uint2 mw1 = *reinterpret_cast<const uint2*>(mpb + (size_t)r1 * (LK / 32) + kt * 2);

        // S = Q K^T
        float s[8][4] = {};
#pragma unroll
        for (int k16 = 0; k16 < 4; k16++) {
#pragma unroll
            for (int nip = 0; nip < 4; nip++) {
                uint32_t b0, b1, b2, b3;
                uint32_t addr = kcB + (uint32_t)((nip * 16 + knRow) * 144
                                                 + (k16 * 2 + kCol) * 16);
                ldsm4(b0, b1, b2, b3, addr);
                mma16(s[2 * nip], qf[k16][0], qf[k16][1], qf[k16][2], qf[k16][3], b0, b1);
                mma16(s[2 * nip + 1], qf[k16][0], qf[k16][1], qf[k16][2], qf[k16][3], b2, b3);
            }
        }

        // mask (bit tests) + scale, row max
        float mx0 = m0, mx1 = m1;
#pragma unroll
        for (int ni = 0; ni < 8; ni++) {
            uint32_t sh0 = ((ni < 4) ? mw0.x : mw0.y) >> ((ni & 3) * 8 + tg * 2);
            uint32_t sh1 = ((ni < 4) ? mw1.x : mw1.y) >> ((ni & 3) * 8 + tg * 2);
            s[ni][0] = (sh0 & 1) ? s[ni][0] * 0.125f : -1e9f;
            s[ni][1] = (sh0 & 2) ? s[ni][1] * 0.125f : -1e9f;
            s[ni][2] = (sh1 & 1) ? s[ni][2] * 0.125f : -1e9f;
            s[ni][3] = (sh1 & 2) ? s[ni][3] * 0.125f : -1e9f;
            mx0 = fmaxf(mx0, fmaxf(s[ni][0], s[ni][1]));
            mx1 = fmaxf(mx1, fmaxf(s[ni][2], s[ni][3]));
        }
        mx0 = fmaxf(mx0, __shfl_xor_sync(0xffffffff, mx0, 1));
        mx0 = fmaxf(mx0, __shfl_xor_sync(0xffffffff, mx0, 2));
        mx1 = fmaxf(mx1, __shfl_xor_sync(0xffffffff, mx1, 1));
        mx1 = fmaxf(mx1, __shfl_xor_sync(0xffffffff, mx1, 2));

        float al0 = __expf(m0 - mx0), al1 = __expf(m1 - mx1);
        float ls0 = 0.f, ls1 = 0.f;
#pragma unroll
        for (int ni = 0; ni < 8; ni++) {
            s[ni][0] = __expf(s[ni][0] - mx0);
            s[ni][1] = __expf(s[ni][1] - mx0);
            s[ni][2] = __expf(s[ni][2] - mx1);
            s[ni][3] = __expf(s[ni][3] - mx1);
            ls0 += s[ni][0] + s[ni][1];
            ls1 += s[ni][2] + s[ni][3];
        }
        ls0 += __shfl_xor_sync(0xffffffff, ls0, 1);
        ls0 += __shfl_xor_sync(0xffffffff, ls0, 2);
        ls1 += __shfl_xor_sync(0xffffffff, ls1, 1);
        ls1 += __shfl_xor_sync(0xffffffff, ls1, 2);
        l0 = l0 * al0 + ls0;  m0 = mx0;
        l1 = l1 * al1 + ls1;  m1 = mx1;

        // rescale accumulator; pack P to fp16 A-fragments (registers only)
        uint32_t pa[4][4];
#pragma unroll
        for (int ni = 0; ni < 8; ni++) {
            acc[ni][0] *= al0; acc[ni][1] *= al0;
            acc[ni][2] *= al1; acc[ni][3] *= al1;
        }
#pragma unroll
        for (int k16 = 0; k16 < 4; k16++) {
            pa[k16][0] = ph2(s[2 * k16][0], s[2 * k16][1]);
            pa[k16][1] = ph2(s[2 * k16][2], s[2 * k16][3]);
            pa[k16][2] = ph2(s[2 * k16 + 1][0], s[2 * k16 + 1][1]);
            pa[k16][3] = ph2(s[2 * k16 + 1][2], s[2 * k16 + 1][3]);
        }

        // O += P @ V
#pragma unroll
        for (int k16 = 0; k16 < 4; k16++) {
#pragma unroll
            for (int nip = 0; nip < 4; nip++) {
                uint32_t b0, b1, b2, b3;
                uint32_t addr = vcB + (uint32_t)((k16 * 16 + vRow) * 144
                                                 + (nip * 2 + vCol) * 16);
                ldsm4t(b0, b1, b2, b3, addr);
                mma16(acc[2 * nip], pa[k16][0], pa[k16][1], pa[k16][2], pa[k16][3], b0, b1);
                mma16(acc[2 * nip + 1], pa[k16][0], pa[k16][1], pa[k16][2], pa[k16][3], b2, b3);
            }
        }

        cp_wait0();
        __syncthreads();
    }

    // epilogue: ctx fp16
    {
        float inv0 = 1.f / l0, inv1 = 1.f / l1;
#pragma unroll
        for (int ni = 0; ni < 8; ni++) {
            int c = ni * 8 + tg * 2;
            size_t o0 = (size_t)(b * LQ + q0 + r0) * HH + h * HD + c;
            size_t o1 = (size_t)(b * LQ + q0 + r1) * HH + h * HD + c;
            *reinterpret_cast<__half2*>(ctx + o0) =
                __floats2half2_rn(acc[ni][0] * inv0, acc[ni][1] * inv0);
            *reinterpret_cast<__half2*>(ctx + o1) =
                __floats2half2_rn(acc[ni][2] * inv1, acc[ni][3] * inv1);
        }
    }
}

// -------------------- LayerNorm (warp-per-row, shuffle-only) --------------------
__global__ __launch_bounds__(256) void ln_kernel(
    const float* __restrict__ X, const float* __restrict__ gg,
    const float* __restrict__ bta, float* __restrict__ out)
{
    int warp = threadIdx.x >> 5, lane = threadIdx.x & 31;
    int row = blockIdx.x * 8 + warp;
    const float4* xr = reinterpret_cast<const float4*>(X + (size_t)row * HH);
    float4 v[8];
    float s = 0.f;
#pragma unroll
    for (int c = 0; c < 8; c++) {
        v[c] = xr[c * 32 + lane];
        s += v[c].x + v[c].y + v[c].z + v[c].w;
    }
#pragma unroll
    for (int o = 16; o > 0; o >>= 1) s += __shfl_xor_sync(0xffffffff, s, o);
    float mean = s * (1.f / (float)HH);
    float d2 = 0.f;
#pragma unroll
    for (int c = 0; c < 8; c++) {
        float dx = v[c].x - mean, dy = v[c].y - mean;
        float dz = v[c].z - mean, dw = v[c].w - mean;
        d2 += dx * dx + dy * dy + dz * dz + dw * dw;
    }
#pragma unroll
    for (int o = 16; o > 0; o >>= 1) d2 += __shfl_xor_sync(0xffffffff, d2, o);
    float rstd = rsqrtf(d2 * (1.f / (float)HH) + EPS);
    float4* orow = reinterpret_cast<float4*>(out + (size_t)row * HH);
#pragma unroll
    for (int c = 0; c < 8; c++) {
        float4 g4 = reinterpret_cast<const float4*>(gg)[c * 32 + lane];
        float4 b4 = reinterpret_cast<const float4*>(bta)[c * 32 + lane];
        float4 o4;
        o4.x = (v[c].x - mean) * rstd * g4.x + b4.x;
        o4.y = (v[c].y - mean) * rstd * g4.y + b4.y;
        o4.z = (v[c].z - mean) * rstd * g4.z + b4.z;
        o4.w = (v[c].w - mean) * rstd * g4.w + b4.w;
        orow[c * 32 + lane] = o4;
    }
}

// -------------------- launch --------------------
extern "C" void kernel_launch(void* const* d_in, const int* in_sizes, int n_in,
                              void* d_out, int out_size)
{
    const float* query = (const float*)d_in[0];
    const float* key   = (const float*)d_in[1];
    const float* value = (const float*)d_in[2];
    const int*   mask  = (const int*)d_in[3];
    const float* bq = (const float*)d_in[5];
    const float* bk = (const float*)d_in[7];
    const float* bv = (const float*)d_in[9];
    const float* bo = (const float*)d_in[11];
    const float* ln_g = (const float*)d_in[12];
    const float* ln_b = (const float*)d_in[13];
    float* out = (float*)d_out;

    __half *pq16, *pk16, *pv16, *pwq, *pwk, *pwv, *pwo, *pQ16, *pK16, *pV16, *pctx;
    float *pX;
    uint32_t* pmm;
    cudaGetSymbolAddress((void**)&pq16, c_q16);
    cudaGetSymbolAddress((void**)&pk16, c_k16);
    cudaGetSymbolAddress((void**)&pv16, c_v16);
    cudaGetSymbolAddress((void**)&pwq, w16q);
    cudaGetSymbolAddress((void**)&pwk, w16k);
    cudaGetSymbolAddress((void**)&pwv, w16v);
    cudaGetSymbolAddress((void**)&pwo, w16o);
    cudaGetSymbolAddress((void**)&pQ16, g_Q16);
    cudaGetSymbolAddress((void**)&pK16, g_K16);
    cudaGetSymbolAddress((void**)&pV16, g_V16);
    cudaGetSymbolAddress((void**)&pctx, g_ctx16);
    cudaGetSymbolAddress((void**)&pX, g_x);
    cudaGetSymbolAddress((void**)&pmm, g_mmask);

    cudaFuncSetAttribute(attn_f16,
                         cudaFuncAttributeMaxDynamicSharedMemorySize, A3_BYTES);
    cudaFuncSetAttribute(gemm_f16<128>,
                         cudaFuncAttributeMaxDynamicSharedMemorySize, G128_SMEM);
    cudaFuncSetAttribute(gemm_f16<64>,
                         cudaFuncAttributeMaxDynamicSharedMemorySize, G64_SMEM);

    // 1) convert inputs + weights to fp16; pack mask bits
    CvtArgs ca;
    ca.src[0] = query; ca.dst[0] = pq16;
    ca.src[1] = key;   ca.dst[1] = pk16;
    ca.src[2] = value; ca.dst[2] = pv16;
    ca.src[3] = (const float*)d_in[4];  ca.dst[3] = pwq;
    ca.src[4] = (const float*)d_in[6];  ca.dst[4] = pwk;
    ca.src[5] = (const float*)d_in[8];  ca.dst[5] = pwv;
    ca.src[6] = (const float*)d_in[10]; ca.dst[6] = pwo;
    int bs[8] = {0, 1024, 3072, 5120, 5632, 6144, 6656, 7168};
    for (int i = 0; i < 8; i++) ca.bstart[i] = bs[i];
    cvt_f16<<<7168, 256>>>(ca);
    mask_pack<<<512, 256>>>(mask, pmm);

    // 2) fused Q/K/V projections (fp16 mma, BK=64, ldsm, 3-stage)
    GemmArgs qa;
    qa.nseg = 3;
    qa.seg[0] = {pq16, pwq, bq, nullptr, (void*)pQ16, 1, 0};
    qa.seg[1] = {pk16, pwk, bk, nullptr, (void*)pK16, 1, 16};
    qa.seg[2] = {pv16, pwv, bv, nullptr, (void*)pV16, 1, 48};
    gemm_f16<128><<<dim3(HH / 128, 80), 256, G128_SMEM>>>(qa);

    // 3) attention (packed mask)
    attn_f16<<<dim3(LQ / 128, NH, BB), 256, A3_BYTES>>>(pQ16, pK16, pV16, pmm, pctx);

    // 4) output projection + residual
    GemmArgs oa;
    oa.nseg = 1;
    oa.seg[0] = {pctx, pwo, bo, query, (void*)pX, 0, 0};
    oa.seg[1] = oa.seg[0];
    oa.seg[2] = oa.seg[0];
    gemm_f16<64><<<dim3(HH / 64, 16), 256, G64_SMEM>>>(oa);

    // 5) layernorm (warp per row)
    ln_kernel<<<BB * LQ / 8, 256>>>(pX, ln_g, ln_b, out);
}

// round 15
// speedup vs baseline: 1.3839x; 1.0620x over previous
#include <cuda_runtime.h>
#include <cuda_fp16.h>
#include <math.h>
#include <stdint.h>

// Problem constants (fixed shapes)
#define BB   2
#define LQ   1024
#define LK   2048
#define HH   1024
#define NH   16
#define HD   64
#define EPS  1e-5f
#define QSCALE 0.180336880f     // 0.125 * log2(e)

// -------------------- scratch --------------------
__device__ __align__(256) __half c_q16[BB * LQ * HH];
__device__ __align__(256) __half c_k16[BB * LK * HH];
__device__ __align__(256) __half c_v16[BB * LK * HH];
__device__ __align__(256) __half w16q[HH * HH];
__device__ __align__(256) __half w16k[HH * HH];
__device__ __align__(256) __half w16v[HH * HH];
__device__ __align__(256) __half w16o[HH * HH];
__device__ __align__(256) __half g_Q16[BB * LQ * HH];
__device__ __align__(256) __half g_K16[BB * LK * HH];
__device__ __align__(256) __half g_V16[BB * LK * HH];
__device__ __align__(256) __half g_ctx16[BB * LQ * HH];
__device__ __align__(256) float  g_x[BB * LQ * HH];
__device__ __align__(256) uint32_t g_mmask[BB * LQ * LK / 32];

// -------------------- helpers --------------------
__device__ __forceinline__ uint32_t smaddr(const void* p) {
    return (uint32_t)__cvta_generic_to_shared(p);
}
__device__ __forceinline__ void cp16(uint32_t dst, const void* src) {
    asm volatile("cp.async.cg.shared.global [%0], [%1], 16;" :: "r"(dst), "l"(src));
}
__device__ __forceinline__ void cp_commit() {
    asm volatile("cp.async.commit_group;");
}
__device__ __forceinline__ void cp_wait0() {
    asm volatile("cp.async.wait_group 0;");
}
__device__ __forceinline__ void cp_wait1() {
    asm volatile("cp.async.wait_group 1;");
}
__device__ __forceinline__ void mma16(float* c,
    uint32_t a0, uint32_t a1, uint32_t a2, uint32_t a3,
    uint32_t b0, uint32_t b1)
{
    asm volatile(
        "mma.sync.aligned.m16n8k16.row.col.f32.f16.f16.f32 "
        "{%0,%1,%2,%3},{%4,%5,%6,%7},{%8,%9},{%0,%1,%2,%3};"
        : "+f"(c[0]), "+f"(c[1]), "+f"(c[2]), "+f"(c[3])
        : "r"(a0), "r"(a1), "r"(a2), "r"(a3), "r"(b0), "r"(b1));
}
__device__ __forceinline__ void ldsm4(uint32_t& r0, uint32_t& r1, uint32_t& r2,
                                      uint32_t& r3, uint32_t a)
{
    asm volatile("ldmatrix.sync.aligned.m8n8.x4.shared.b16 {%0,%1,%2,%3}, [%4];"
                 : "=r"(r0), "=r"(r1), "=r"(r2), "=r"(r3) : "r"(a));
}
__device__ __forceinline__ void ldsm4t(uint32_t& r0, uint32_t& r1, uint32_t& r2,
                                       uint32_t& r3, uint32_t a)
{
    asm volatile("ldmatrix.sync.aligned.m8n8.x4.trans.shared.b16 {%0,%1,%2,%3}, [%4];"
                 : "=r"(r0), "=r"(r1), "=r"(r2), "=r"(r3) : "r"(a));
}
__device__ __forceinline__ uint32_t ph2(float x, float y) {
    __half2 h = __floats2half2_rn(x, y);
    return *reinterpret_cast<uint32_t*>(&h);
}
__device__ __forceinline__ float ex2(float x) {
    float r;
    asm("ex2.approx.ftz.f32 %0, %1;" : "=f"(r) : "f"(x));
    return r;
}

// -------------------- fp32 -> fp16 conversion (with per-segment scale) ---------
struct CvtArgs {
    const float* src[7];
    __half* dst[7];
    float scale[7];
    int bstart[8];
};

__global__ __launch_bounds__(256) void cvt_f16(CvtArgs a)
{
    int bid = blockIdx.x, s = 0;
#pragma unroll
    for (int i = 1; i < 7; i++) if (bid >= a.bstart[i]) s = i;
    float sc = a.scale[s];
    int off = (bid - a.bstart[s]) * 2048 + threadIdx.x * 8;
    float4 v0 = *reinterpret_cast<const float4*>(a.src[s] + off);
    float4 v1 = *reinterpret_cast<const float4*>(a.src[s] + off + 4);
    __half2 h0 = __floats2half2_rn(v0.x * sc, v0.y * sc);
    __half2 h1 = __floats2half2_rn(v0.z * sc, v0.w * sc);
    __half2 h2 = __floats2half2_rn(v1.x * sc, v1.y * sc);
    __half2 h3 = __floats2half2_rn(v1.z * sc, v1.w * sc);
    uint4 o;
    o.x = *reinterpret_cast<uint32_t*>(&h0);
    o.y = *reinterpret_cast<uint32_t*>(&h1);
    o.z = *reinterpret_cast<uint32_t*>(&h2);
    o.w = *reinterpret_cast<uint32_t*>(&h3);
    *reinterpret_cast<uint4*>(a.dst[s] + off) = o;
}

// -------------------- mask bit-packing --------------------
__global__ __launch_bounds__(256) void mask_pack(
    const int* __restrict__ mask, uint32_t* __restrict__ mp)
{
    int warpG = (blockIdx.x * 256 + threadIdx.x) >> 5;
    int lane = threadIdx.x & 31;
    size_t base = (size_t)warpG * 1024;
    uint32_t myw = 0;
#pragma unroll
    for (int i = 0; i < 32; i++) {
        int v = mask[base + i * 32 + lane];
        uint32_t bl = __ballot_sync(0xffffffff, v != 0);
        if (lane == i) myw = bl;
    }
    mp[(size_t)warpG * 32 + lane] = myw;
}

// -------------------- fp16 GEMM v3: BK=64, ldsm, 3-stage, smem bias ------------
struct GemmSeg {
    const __half* A; const __half* W;
    const float* bias; const float* residual;
    void* C; int outHalf; int tileStart; float biasScale;
};
struct GemmArgs { GemmSeg seg[3]; int nseg; };

template<int NT>
__global__ __launch_bounds__(256, 2) void gemm_f16(GemmArgs ga)
{
    constexpr int NI = NT / 16;
    constexpr int ASTG = 128 * 36;
    constexpr int BSTG = NT * 36;
    extern __shared__ __align__(16) uint32_t dsm[];
    const uint32_t smA = smaddr(dsm);
    const uint32_t smB = smA + 3 * ASTG * 4;
    float* biasSm = reinterpret_cast<float*>(dsm + 3 * (ASTG + BSTG));

    const int y = blockIdx.y;
    int si = 0;
#pragma unroll
    for (int i = 1; i < 3; i++) if (i < ga.nseg && y >= ga.seg[i].tileStart) si = i;
    const GemmSeg sg = ga.seg[si];

    const int t = threadIdx.x, lane = t & 31, warp = t >> 5;
    const int g = lane >> 2, tg = lane & 3;
    const int wm = warp & 3, wn = warp >> 2;
    const int rowBase = (y - sg.tileStart) * 128, colBase = blockIdx.x * NT;
    const int ti = lane >> 3, r8 = lane & 7;
    const int aRow = ((ti & 1) << 3) + r8, aCol = ti >> 1;
    const int bRow = ((ti >> 1) << 3) + r8, bCol = ti & 1;

    if (t < NT) biasSm[t] = sg.bias[colBase + t] * sg.biasScale;

    auto loadStage = [&](int buf, int k0) {
#pragma unroll
        for (int i = 0; i < 4; i++) {
            int id = t + 256 * i;
            int r = id >> 3, c = id & 7;
            cp16(smA + (uint32_t)(buf * ASTG * 4 + r * 144 + c * 16),
                 sg.A + (size_t)(rowBase + r) * HH + k0 + c * 8);
        }
#pragma unroll
        for (int i = 0; i < NT / 32; i++) {
            int id = t + 256 * i;
            int r = id >> 3, c = id & 7;
            cp16(smB + (uint32_t)(buf * BSTG * 4 + r * 144 + c * 16),
                 sg.W + (size_t)(colBase + r) * HH + k0 + c * 8);
        }
    };

    loadStage(0, 0);  cp_commit();
    loadStage(1, 64); cp_commit();

    float acc[2][NI][4] = {};
    const int nst = HH / 64;

    for (int s = 0; s < nst; s++) {
        if (s + 1 < nst) cp_wait1(); else cp_wait0();
        __syncthreads();
        if (s + 2 < nst) { loadStage((s + 2) % 3, (s + 2) * 64); cp_commit(); }

        const uint32_t aBase = smA + (uint32_t)((s % 3) * ASTG * 4);
        const uint32_t bBase = smB + (uint32_t)((s % 3) * BSTG * 4);

#pragma unroll
        for (int k16 = 0; k16 < 4; k16++) {
            uint32_t a[2][4];
#pragma unroll
            for (int mi = 0; mi < 2; mi++) {
                ldsm4(a[mi][0], a[mi][1], a[mi][2], a[mi][3],
                      aBase + (uint32_t)((wm * 32 + mi * 16 + aRow) * 144
                                         + (k16 * 2 + aCol) * 16));
            }
#pragma unroll
            for (int nip = 0; nip < NI / 2; nip++) {
                uint32_t b0, b1, b2, b3;
                ldsm4(b0, b1, b2, b3,
                      bBase + (uint32_t)((wn * (NT / 2) + nip * 16 + bRow) * 144
                                         + (k16 * 2 + bCol) * 16));
                mma16(acc[0][2 * nip],     a[0][0], a[0][1], a[0][2], a[0][3], b0, b1);
                mma16(acc[0][2 * nip + 1], a[0][0], a[0][1], a[0][2], a[0][3], b2, b3);
                mma16(acc[1][2 * nip],     a[1][0], a[1][1], a[1][2], a[1][3], b0, b1);
                mma16(acc[1][2 * nip + 1], a[1][0], a[1][1], a[1][2], a[1][3], b2, b3);
            }
        }
    }

#pragma unroll
    for (int mi = 0; mi < 2; mi++) {
#pragma unroll
        for (int ni = 0; ni < NI; ni++) {
            int r = rowBase + wm * 32 + mi * 16 + g;
            int cl = wn * (NT / 2) + ni * 8 + tg * 2;
            int c = colBase + cl;
            float b0 = biasSm[cl], b1 = biasSm[cl + 1];
            float v0 = acc[mi][ni][0] + b0, v1 = acc[mi][ni][1] + b1;
            float v2 = acc[mi][ni][2] + b0, v3 = acc[mi][ni][3] + b1;
            if (sg.outHalf) {
                __half* Ch = (__half*)sg.C;
                *reinterpret_cast<__half2*>(Ch + (size_t)r * HH + c) = __floats2half2_rn(v0, v1);
                *reinterpret_cast<__half2*>(Ch + (size_t)(r + 8) * HH + c) = __floats2half2_rn(v2, v3);
            } else {
                float* Cf = (float*)sg.C;
                if (sg.residual) {
                    float2 r0 = *reinterpret_cast<const float2*>(sg.residual + (size_t)r * HH + c);
                    float2 r1 = *reinterpret_cast<const float2*>(sg.residual + (size_t)(r + 8) * HH + c);
                    v0 += r0.x; v1 += r0.y; v2 += r1.x; v3 += r1.y;
                }
                *reinterpret_cast<float2*>(Cf + (size_t)r * HH + c) = make_float2(v0, v1);
                *reinterpret_cast<float2*>(Cf + (size_t)(r + 8) * HH + c) = make_float2(v2, v3);
            }
        }
    }
}

#define G128_SMEM (3 * (128 * 36 + 128 * 36) * 4 + 128 * 4)   // 111104
#define G64_SMEM  (3 * (128 * 36 + 64 * 36) * 4 + 64 * 4)     // 83200

// -------------------- Flash attention v11: log2-domain softmax -----------------
// Q pre-scaled by 0.125*log2e -> S is directly in log2 domain.
// mask = select only; exp = bare ex2.approx; alpha = ex2.
#define K16W 2304
#define V16W 2304
#define A3_BYTES ((2 * K16W + 2 * V16W) * 4)   // 36864 bytes -> 2 CTAs/SM

__global__ __launch_bounds__(256, 2) void attn_f16(
    const __half* __restrict__ Q, const __half* __restrict__ K,
    const __half* __restrict__ V, const uint32_t* __restrict__ mp,
    __half* __restrict__ ctx)
{
    extern __shared__ __align__(16) uint32_t sh[];
    uint32_t* Kw = sh;
    uint32_t* Vw = sh + 2 * K16W;

    const int q0 = blockIdx.x * 128, h = blockIdx.y, b = blockIdx.z;
    const int t = threadIdx.x, lane = t & 31, warp = t >> 5;
    const int g = lane >> 2, tg = lane & 3;
    const int wbase = warp * 16;
    const int ti = lane >> 3, r8 = lane & 7;
    const int knRow = ((ti >> 1) << 3) + r8;
    const int kCol  = ti & 1;
    const int vRow  = ((ti & 1) << 3) + r8;
    const int vCol  = ti >> 1;

    const uint32_t smK = smaddr(Kw), smV = smaddr(Vw);

    // stage Q through the V region, extract fragments
#pragma unroll
    for (int i = 0; i < 4; i++) {
        int id = t + 256 * i;
        int r = id >> 3, c = id & 7;
        cp16(smV + (uint32_t)(r * 144 + c * 16),
             Q + (size_t)(b * LQ + q0 + r) * HH + h * HD + c * 8);
    }
    cp_commit(); cp_wait0(); __syncthreads();

    uint32_t qf[4][4];
    {
        int r0 = wbase + g, r1 = r0 + 8;
#pragma unroll
        for (int k16 = 0; k16 < 4; k16++) {
            qf[k16][0] = Vw[r0 * 36 + k16 * 8 + tg];
            qf[k16][1] = Vw[r1 * 36 + k16 * 8 + tg];
            qf[k16][2] = Vw[r0 * 36 + k16 * 8 + 4 + tg];
            qf[k16][3] = Vw[r1 * 36 + k16 * 8 + 4 + tg];
        }
    }
    __syncthreads();

    auto loadKV = [&](int s, int k0) {
#pragma unroll
        for (int i = 0; i < 2; i++) {
            int id = t + 256 * i;
            int r = id >> 3, c = id & 7;
            size_t gofs = (size_t)(b * LK + k0 + r) * HH + h * HD + c * 8;
            cp16(smK + (uint32_t)(s * K16W * 4 + r * 144 + c * 16), K + gofs);
            cp16(smV + (uint32_t)(s * V16W * 4 + r * 144 + c * 16), V + gofs);
        }
    };
    loadKV(0, 0);
    cp_commit(); cp_wait0(); __syncthreads();

    float acc[8][4] = {};
    float m0 = -1e30f, m1 = -1e30f, l0 = 0.f, l1 = 0.f;
    const uint32_t* mpb = mp + (size_t)(b * LQ + q0) * (LK / 32);
    const int nkt = LK / 64;
    const int r0 = wbase + g, r1 = r0 + 8;

    for (int kt = 0; kt < nkt; kt++) {
        if (kt + 1 < nkt) { loadKV((kt + 1) & 1, (kt + 1) * 64); cp_commit(); }

        const uint32_t kcB = smK + (uint32_t)((kt & 1) * K16W * 4);
        const uint32_t vcB = smV + (uint32_t)((kt & 1) * V16W * 4);

        uint2 mw0 = *reinterpret_cast<const uint2*>(mpb + (size_t)r0 * (LK / 32) + kt * 2);
        uint2 mw1 = *reinterpret_cast<const uint2*>(mpb + (size_t)r1 * (LK / 32) + kt * 2);

        // S = Q K^T   (log2-domain scores: Q pre-scaled)
        float s[8][4] = {};
#pragma unroll
        for (int k16 = 0; k16 < 4; k16++) {
#pragma unroll
            for (int nip = 0; nip < 4; nip++) {
                uint32_t b0, b1, b2, b3;
                uint32_t addr = kcB + (uint32_t)((nip * 16 + knRow) * 144
                                                 + (k16 * 2 + kCol) * 16);
                ldsm4(b0, b1, b2, b3, addr);
                mma16(s[2 * nip], qf[k16][0], qf[k16][1], qf[k16][2], qf[k16][3], b0, b1);
                mma16(s[2 * nip + 1], qf[k16][0], qf[k16][1], qf[k16][2], qf[k16][3], b2, b3);
            }
        }

        // mask (pure select) + row max
        float mx0 = m0, mx1 = m1;
#pragma unroll
        for (int ni = 0; ni < 8; ni++) {
            uint32_t sh0 = ((ni < 4) ? mw0.x : mw0.y) >> ((ni & 3) * 8 + tg * 2);
            uint32_t sh1 = ((ni < 4) ? mw1.x : mw1.y) >> ((ni & 3) * 8 + tg * 2);
            s[ni][0] = (sh0 & 1) ? s[ni][0] : -1e9f;
            s[ni][1] = (sh0 & 2) ? s[ni][1] : -1e9f;
            s[ni][2] = (sh1 & 1) ? s[ni][2] : -1e9f;
            s[ni][3] = (sh1 & 2) ? s[ni][3] : -1e9f;
            mx0 = fmaxf(mx0, fmaxf(s[ni][0], s[ni][1]));
            mx1 = fmaxf(mx1, fmaxf(s[ni][2], s[ni][3]));
        }
        mx0 = fmaxf(mx0, __shfl_xor_sync(0xffffffff, mx0, 1));
        mx0 = fmaxf(mx0, __shfl_xor_sync(0xffffffff, mx0, 2));
        mx1 = fmaxf(mx1, __shfl_xor_sync(0xffffffff, mx1, 1));
        mx1 = fmaxf(mx1, __shfl_xor_sync(0xffffffff, mx1, 2));

        float al0 = ex2(m0 - mx0), al1 = ex2(m1 - mx1);
        float ls0 = 0.f, ls1 = 0.f;
#pragma unroll
        for (int ni = 0; ni < 8; ni++) {
            s[ni][0] = ex2(s[ni][0] - mx0);
            s[ni][1] = ex2(s[ni][1] - mx0);
            s[ni][2] = ex2(s[ni][2] - mx1);
            s[ni][3] = ex2(s[ni][3] - mx1);
            ls0 += s[ni][0] + s[ni][1];
            ls1 += s[ni][2] + s[ni][3];
        }
        ls0 += __shfl_xor_sync(0xffffffff, ls0, 1);
        ls0 += __shfl_xor_sync(0xffffffff, ls0, 2);
        ls1 += __shfl_xor_sync(0xffffffff, ls1, 1);
        ls1 += __shfl_xor_sync(0xffffffff, ls1, 2);
        l0 = l0 * al0 + ls0;  m0 = mx0;
        l1 = l1 * al1 + ls1;  m1 = mx1;

        // rescale accumulator; pack P to fp16 A-fragments
        uint32_t pa[4][4];
#pragma unroll
        for (int ni = 0; ni < 8; ni++) {
            acc[ni][0] *= al0; acc[ni][1] *= al0;
            acc[ni][2] *= al1; acc[ni][3] *= al1;
        }
#pragma unroll
        for (int k16 = 0; k16 < 4; k16++) {
            pa[k16][0] = ph2(s[2 * k16][0], s[2 * k16][1]);
            pa[k16][1] = ph2(s[2 * k16][2], s[2 * k16][3]);
            pa[k16][2] = ph2(s[2 * k16 + 1][0], s[2 * k16 + 1][1]);
            pa[k16][3] = ph2(s[2 * k16 + 1][2], s[2 * k16 + 1][3]);
        }

        // O += P @ V
#pragma unroll
        for (int k16 = 0; k16 < 4; k16++) {
#pragma unroll
            for (int nip = 0; nip < 4; nip++) {
                uint32_t b0, b1, b2, b3;
                uint32_t addr = vcB + (uint32_t)((k16 * 16 + vRow) * 144
                                                 + (nip * 2 + vCol) * 16);
                ldsm4t(b0, b1, b2, b3, addr);
                mma16(acc[2 * nip], pa[k16][0], pa[k16][1], pa[k16][2], pa[k16][3], b0, b1);
                mma16(acc[2 * nip + 1], pa[k16][0], pa[k16][1], pa[k16][2], pa[k16][3], b2, b3);
            }
        }

        cp_wait0();
        __syncthreads();
    }

    // epilogue: ctx fp16
    {
        float inv0 = 1.f / l0, inv1 = 1.f / l1;
#pragma unroll
        for (int ni = 0; ni < 8; ni++) {
            int c = ni * 8 + tg * 2;
            size_t o0 = (size_t)(b * LQ + q0 + r0) * HH + h * HD + c;
            size_t o1 = (size_t)(b * LQ + q0 + r1) * HH + h * HD + c;
            *reinterpret_cast<__half2*>(ctx + o0) =
                __floats2half2_rn(acc[ni][0] * inv0, acc[ni][1] * inv0);
            *reinterpret_cast<__half2*>(ctx + o1) =
                __floats2half2_rn(acc[ni][2] * inv1, acc[ni][3] * inv1);
        }
    }
}

// -------------------- LayerNorm (warp-per-row, shuffle-only) --------------------
__global__ __launch_bounds__(256) void ln_kernel(
    const float* __restrict__ X, const float* __restrict__ gg,
    const float* __restrict__ bta, float* __restrict__ out)
{
    int warp = threadIdx.x >> 5, lane = threadIdx.x & 31;
    int row = blockIdx.x * 8 + warp;
    const float4* xr = reinterpret_cast<const float4*>(X + (size_t)row * HH);
    float4 v[8];
    float s = 0.f;
#pragma unroll
    for (int c = 0; c < 8; c++) {
        v[c] = xr[c * 32 + lane];
        s += v[c].x + v[c].y + v[c].z + v[c].w;
    }
#pragma unroll
    for (int o = 16; o > 0; o >>= 1) s += __shfl_xor_sync(0xffffffff, s, o);
    float mean = s * (1.f / (float)HH);
    float d2 = 0.f;
#pragma unroll
    for (int c = 0; c < 8; c++) {
        float dx = v[c].x - mean, dy = v[c].y - mean;
        float dz = v[c].z - mean, dw = v[c].w - mean;
        d2 += dx * dx + dy * dy + dz * dz + dw * dw;
    }
#pragma unroll
    for (int o = 16; o > 0; o >>= 1) d2 += __shfl_xor_sync(0xffffffff, d2, o);
    float rstd = rsqrtf(d2 * (1.f / (float)HH) + EPS);
    float4* orow = reinterpret_cast<float4*>(out + (size_t)row * HH);
#pragma unroll
    for (int c = 0; c < 8; c++) {
        float4 g4 = reinterpret_cast<const float4*>(gg)[c * 32 + lane];
        float4 b4 = reinterpret_cast<const float4*>(bta)[c * 32 + lane];
        float4 o4;
        o4.x = (v[c].x - mean) * rstd * g4.x + b4.x;
        o4.y = (v[c].y - mean) * rstd * g4.y + b4.y;
        o4.z = (v[c].z - mean) * rstd * g4.z + b4.z;
        o4.w = (v[c].w - mean) * rstd * g4.w + b4.w;
        orow[c * 32 + lane] = o4;
    }
}

// -------------------- launch --------------------
extern "C" void kernel_launch(void* const* d_in, const int* in_sizes, int n_in,
                              void* d_out, int out_size)
{
    const float* query = (const float*)d_in[0];
    const float* key   = (const float*)d_in[1];
    const float* value = (const float*)d_in[2];
    const int*   mask  = (const int*)d_in[3];
    const float* bq = (const float*)d_in[5];
    const float* bk = (const float*)d_in[7];
    const float* bv = (const float*)d_in[9];
    const float* bo = (const float*)d_in[11];
    const float* ln_g = (const float*)d_in[12];
    const float* ln_b = (const float*)d_in[13];
    float* out = (float*)d_out;

    __half *pq16, *pk16, *pv16, *pwq, *pwk, *pwv, *pwo, *pQ16, *pK16, *pV16, *pctx;
    float *pX;
    uint32_t* pmm;
    cudaGetSymbolAddress((void**)&pq16, c_q16);
    cudaGetSymbolAddress((void**)&pk16, c_k16);
    cudaGetSymbolAddress((void**)&pv16, c_v16);
    cudaGetSymbolAddress((void**)&pwq, w16q);
    cudaGetSymbolAddress((void**)&pwk, w16k);
    cudaGetSymbolAddress((void**)&pwv, w16v);
    cudaGetSymbolAddress((void**)&pwo, w16o);
    cudaGetSymbolAddress((void**)&pQ16, g_Q16);
    cudaGetSymbolAddress((void**)&pK16, g_K16);
    cudaGetSymbolAddress((void**)&pV16, g_V16);
    cudaGetSymbolAddress((void**)&pctx, g_ctx16);
    cudaGetSymbolAddress((void**)&pX, g_x);
    cudaGetSymbolAddress((void**)&pmm, g_mmask);

    cudaFuncSetAttribute(attn_f16,
                         cudaFuncAttributeMaxDynamicSharedMemorySize, A3_BYTES);
    cudaFuncSetAttribute(gemm_f16<128>,
                         cudaFuncAttributeMaxDynamicSharedMemorySize, G128_SMEM);
    cudaFuncSetAttribute(gemm_f16<64>,
                         cudaFuncAttributeMaxDynamicSharedMemorySize, G64_SMEM);

    // 1) convert inputs + weights to fp16 (Wq scaled by 0.125*log2e); pack mask
    CvtArgs ca;
    ca.src[0] = query; ca.dst[0] = pq16; ca.scale[0] = 1.f;
    ca.src[1] = key;   ca.dst[1] = pk16; ca.scale[1] = 1.f;
    ca.src[2] = value; ca.dst[2] = pv16; ca.scale[2] = 1.f;
    ca.src[3] = (const float*)d_in[4];  ca.dst[3] = pwq; ca.scale[3] = QSCALE;
    ca.src[4] = (const float*)d_in[6];  ca.dst[4] = pwk; ca.scale[4] = 1.f;
    ca.src[5] = (const float*)d_in[8];  ca.dst[5] = pwv; ca.scale[5] = 1.f;
    ca.src[6] = (const float*)d_in[10]; ca.dst[6] = pwo; ca.scale[6] = 1.f;
    int bs[8] = {0, 1024, 3072, 5120, 5632, 6144, 6656, 7168};
    for (int i = 0; i < 8; i++) ca.bstart[i] = bs[i];
    cvt_f16<<<7168, 256>>>(ca);
    mask_pack<<<512, 256>>>(mask, pmm);

    // 2) fused Q/K/V projections (bq scaled to match scaled Wq)
    GemmArgs qa;
    qa.nseg = 3;
    qa.seg[0] = {pq16, pwq, bq, nullptr, (void*)pQ16, 1, 0,  QSCALE};
    qa.seg[1] = {pk16, pwk, bk, nullptr, (void*)pK16, 1, 16, 1.f};
    qa.seg[2] = {pv16, pwv, bv, nullptr, (void*)pV16, 1, 48, 1.f};
    gemm_f16<128><<<dim3(HH / 128, 80), 256, G128_SMEM>>>(qa);

    // 3) attention (log2-domain softmax)
    attn_f16<<<dim3(LQ / 128, NH, BB), 256, A3_BYTES>>>(pQ16, pK16, pV16, pmm, pctx);

    // 4) output projection + residual
    GemmArgs oa;
    oa.nseg = 1;
    oa.seg[0] = {pctx, pwo, bo, query, (void*)pX, 0, 0, 1.f};
    oa.seg[1] = oa.seg[0];
    oa.seg[2] = oa.seg[0];
    gemm_f16<64><<<dim3(HH / 64, 16), 256, G64_SMEM>>>(oa);

    // 5) layernorm (warp per row)
    ln_kernel<<<BB * LQ / 8, 256>>>(pX, ln_g, ln_b, out);
}